// round 10
// baseline (speedup 1.0000x reference)
#include <cuda_runtime.h>
#include <cuda_bf16.h>
#include <cstdint>

#define N_NODES 100000
#define N_EDGES 1600000
#define SCAN_CHUNKS 98            // ceil(100000/1024)

// ---------------- scratch (device globals; no allocations) ----------------
// g_cnt is zero at process start (static zero-init) and re-zeroed by each
// fill_kernel call for the next invocation (same work every call).
__device__ int   g_cnt[N_NODES];                 // degree histogram
__device__ int   g_rank[N_EDGES];                // per-edge rank within its dst
__device__ int   g_part[SCAN_CHUNKS * 1024];     // per-chunk exclusive scan
__device__ int   g_ctot[SCAN_CHUNKS];            // chunk totals
__device__ int   g_rowptr[N_NODES + 1];          // CSR row pointers
__device__ int   g_col[N_EDGES];                 // CSR column (src) indices
__device__ float g_t1[(size_t)N_NODES * 64];     // x @ W1n
__device__ float g_u1[(size_t)N_NODES * 64];     // x @ W1s
__device__ float g_t2[(size_t)N_NODES * 32];     // h @ W2n
__device__ float g_u2[(size_t)N_NODES * 32];     // h @ W2s

// inline edge-width detection: int64 values < 2^31 have zero high words.
__device__ __forceinline__ int detect_is64(const int* ei32) {
    return (ei32[1] == 0 && ei32[3] == 0 && ei32[5] == 0 && ei32[7] == 0) ? 1 : 0;
}

// ---------------- CSR build ----------------
__global__ void count_kernel(const void* __restrict__ ei, int E) {
    int t = blockIdx.x * blockDim.x + threadIdx.x;
    int e0 = t * 2;
    if (e0 >= E) return;
    int is64 = detect_is64((const int*)ei);
    int d0, d1 = -1;
    if (is64) {
        const long long* p = (const long long*)ei + E;
        d0 = (int)p[e0];
        if (e0 + 1 < E) d1 = (int)p[e0 + 1];
    } else {
        const int* p = (const int*)ei + E;
        d0 = p[e0];
        if (e0 + 1 < E) d1 = p[e0 + 1];
    }
    int r0 = atomicAdd(&g_cnt[d0], 1);
    g_rank[e0] = r0;
    if (d1 >= 0) {
        int r1 = atomicAdd(&g_cnt[d1], 1);
        g_rank[e0 + 1] = r1;
    }
}

__global__ void scan1_kernel() {        // per-chunk exclusive scan, 1024 threads
    __shared__ int s[1024];
    int tid = threadIdx.x;
    int i = blockIdx.x * 1024 + tid;
    int v = (i < N_NODES) ? g_cnt[i] : 0;
    s[tid] = v;
    __syncthreads();
    #pragma unroll
    for (int off = 1; off < 1024; off <<= 1) {
        int t = (tid >= off) ? s[tid - off] : 0;
        __syncthreads();
        s[tid] += t;
        __syncthreads();
    }
    g_part[i] = s[tid] - v;             // exclusive
    if (tid == 1023) g_ctot[blockIdx.x] = s[1023];
}

__global__ void scan3_kernel() {        // adds chunk offsets (each block scans totals)
    __shared__ int s[128];
    int tid = threadIdx.x;
    if (tid < 128) {
        int v = (tid < SCAN_CHUNKS) ? g_ctot[tid] : 0;
        s[tid] = v;
    }
    __syncthreads();
    #pragma unroll
    for (int off = 1; off < 128; off <<= 1) {
        int t = (tid < 128 && tid >= off) ? s[tid - off] : 0;
        __syncthreads();
        if (tid < 128) s[tid] += t;
        __syncthreads();
    }
    int coff = (blockIdx.x == 0) ? 0 : s[blockIdx.x - 1];
    int i = blockIdx.x * 1024 + tid;
    if (i < N_NODES) g_rowptr[i] = g_part[i] + coff;
    if (blockIdx.x == 0 && tid == 0) g_rowptr[N_NODES] = s[SCAN_CHUNKS - 1];
}

// fill: pos = rowptr[dst] + rank[e] — no atomics. Also re-zeros g_cnt.
__global__ void fill_kernel(const void* __restrict__ ei, int E) {
    int t = blockIdx.x * blockDim.x + threadIdx.x;
    if (t < N_NODES / 4) ((int4*)g_cnt)[t] = make_int4(0, 0, 0, 0);
    int e0 = t * 2;
    if (e0 >= E) return;
    int is64 = detect_is64((const int*)ei);
    int s0, d0, s1 = -1, d1 = -1;
    if (is64) {
        const long long* p = (const long long*)ei;
        s0 = (int)p[e0]; d0 = (int)p[E + e0];
        if (e0 + 1 < E) { s1 = (int)p[e0 + 1]; d1 = (int)p[E + e0 + 1]; }
    } else {
        const int* p = (const int*)ei;
        s0 = p[e0]; d0 = p[E + e0];
        if (e0 + 1 < E) { s1 = p[e0 + 1]; d1 = p[E + e0 + 1]; }
    }
    int p0 = g_rowptr[d0] + g_rank[e0];
    g_col[p0] = s0;
    if (d1 >= 0) {
        int p1 = g_rowptr[d1] + g_rank[e0 + 1];
        g_col[p1] = s1;
    }
}

// ---------------- layer-1 GEMM: [t1|u1] = x @ [W1n|W1s] ----------------
#define FMA2(acc, a2, b2) \
    asm("fma.rn.f32x2 %0, %1, %2, %0;" : "+l"(acc) : "l"(a2), "l"(b2))

__global__ __launch_bounds__(256, 2)
void gemmA_kernel(const float* __restrict__ src,
                  const float* __restrict__ Wa,   // [64, 64]
                  const float* __restrict__ Wb) { // [64, 64]
    constexpr int OUT = 128, TPN = 8, NB = 64, HALF = 32, FP = 33;
    __shared__ float sF[NB * FP];
    __shared__ float sW[32 * OUT];

    int tid = threadIdx.x;
    int base = blockIdx.x * NB;
    int ln = tid / TPN;
    int q  = tid % TPN;
    int k4 = tid & 7;

    int r_[2], nc_[2];
    #pragma unroll
    for (int it = 0; it < 2; it++) {
        r_[it] = (tid + it * 256) >> 3;
        int n = base + r_[it];
        nc_[it] = (n < N_NODES) ? n : (N_NODES - 1);
    }
    float4 pf[2], pw[4];

    auto load_chunk = [&](int c) {
        #pragma unroll
        for (int it = 0; it < 2; it++)
            pf[it] = *(const float4*)(src + (size_t)nc_[it] * 64 + c * 32 + k4 * 4);
        #pragma unroll
        for (int iw = 0; iw < 4; iw++) {
            int idx = tid + iw * 256;
            int kk = idx / 32, jq = idx % 32;
            int k = c * 32 + kk;
            const float* wsrc = (jq < 16) ? (Wa + k * 64 + jq * 4)
                                          : (Wb + k * 64 + jq * 4 - 64);
            pw[iw] = *(const float4*)wsrc;
        }
    };
    auto store_stage = [&]() {
        #pragma unroll
        for (int it = 0; it < 2; it++) {
            float* d = sF + r_[it] * FP + k4 * 4;
            d[0] = pf[it].x; d[1] = pf[it].y; d[2] = pf[it].z; d[3] = pf[it].w;
        }
        #pragma unroll
        for (int iw = 0; iw < 4; iw++)
            ((float4*)sW)[tid + iw * 256] = pw[iw];
    };

    load_chunk(0);
    store_stage();
    __syncthreads();

    unsigned long long acc0[8] = {}, acc1[8] = {};
    const float* fp0 = sF + ln * FP;
    const float* fp1 = sF + (ln + HALF) * FP;
    const float* wq  = sW + (q << 2);

    #pragma unroll 1
    for (int c = 0; c < 2; c++) {
        if (c < 1) load_chunk(1);
        #pragma unroll 8
        for (int kk = 0; kk < 32; kk++) {
            float f0 = fp0[kk], f1 = fp1[kk];
            unsigned long long f0d, f1d;
            asm("mov.b64 %0, {%1,%1};" : "=l"(f0d) : "f"(f0));
            asm("mov.b64 %0, {%1,%1};" : "=l"(f1d) : "f"(f1));
            const float* wr = wq + kk * OUT;
            #pragma unroll
            for (int j8 = 0; j8 < 4; j8++) {
                ulonglong2 w = *(const ulonglong2*)(wr + j8 * 32);
                FMA2(acc0[j8 * 2],     f0d, w.x);
                FMA2(acc0[j8 * 2 + 1], f0d, w.y);
                FMA2(acc1[j8 * 2],     f1d, w.x);
                FMA2(acc1[j8 * 2 + 1], f1d, w.y);
            }
        }
        __syncthreads();
        if (c < 1) { store_stage(); __syncthreads(); }
    }

    int n0 = base + ln, n1 = base + ln + HALF;
    #pragma unroll
    for (int j8 = 0; j8 < 4; j8++) {
        int jb = j8 * 32 + (q << 2);
        float* dst = (jb < 64) ? g_t1 : g_u1;
        int joff = jb & 63;
        if (n0 < N_NODES) {
            float o[4];
            asm("mov.b64 {%0,%1}, %2;" : "=f"(o[0]), "=f"(o[1]) : "l"(acc0[j8 * 2]));
            asm("mov.b64 {%0,%1}, %2;" : "=f"(o[2]), "=f"(o[3]) : "l"(acc0[j8 * 2 + 1]));
            *(float4*)(dst + (size_t)n0 * 64 + joff) = *(float4*)o;
        }
        if (n1 < N_NODES) {
            float o[4];
            asm("mov.b64 {%0,%1}, %2;" : "=f"(o[0]), "=f"(o[1]) : "l"(acc1[j8 * 2]));
            asm("mov.b64 {%0,%1}, %2;" : "=f"(o[2]), "=f"(o[3]) : "l"(acc1[j8 * 2 + 1]));
            *(float4*)(dst + (size_t)n1 * 64 + joff) = *(float4*)o;
        }
    }
}

// ---------------- fused: h-tile = relu(mean(t1)+u1+b1) in smem, then
//                  [t2|u2] = h_tile @ [W2n|W2s] ----------------
// 256 threads, 64 nodes/block. Phase 1: 16 lanes/node gather (4 sequential
// node groups). Phase 2: 4 lanes/node GEMM from smem. g_h never exists.
__global__ __launch_bounds__(256)
void fusedH_kernel(const float* __restrict__ b1,
                   const float* __restrict__ W2n,   // [64, 32]
                   const float* __restrict__ W2s) { // [64, 32]
    constexpr int FP = 65;                 // sH row pitch (odd -> conflict-free)
    __shared__ float sH[64 * FP];          // 16.6KB
    __shared__ float sW[64 * 64];          // 16KB: [k][j], j<32 = W2n, j>=32 = W2s

    int tid = threadIdx.x;
    int base = blockIdx.x * 64;

    // stage weights into registers NOW (in flight during entire gather phase)
    float4 wreg[4];
    #pragma unroll
    for (int iw = 0; iw < 4; iw++) {
        int idx = tid + iw * 256;          // float4 index 0..1023
        int k = idx >> 4, jq = idx & 15;
        const float* wsrc = (jq < 8) ? (W2n + k * 32 + jq * 4)
                                     : (W2s + k * 32 + (jq - 8) * 4);
        wreg[iw] = *(const float4*)wsrc;
    }

    // phase 1: gather-mean + epilogue into sH
    int c  = tid & 15;
    int g16 = tid >> 4;
    float4 bb = *(const float4*)(b1 + c * 4);
    #pragma unroll 1
    for (int it = 0; it < 4; it++) {
        int ln = g16 + it * 16;
        int n = base + ln;
        if (n < N_NODES) {
            int start = g_rowptr[n], end = g_rowptr[n + 1];
            float4 acc = make_float4(0.f, 0.f, 0.f, 0.f);
            int i = start;
            for (; i + 3 < end; i += 4) {
                int s0 = g_col[i], s1 = g_col[i + 1], s2 = g_col[i + 2], s3 = g_col[i + 3];
                float4 v0 = *(const float4*)(g_t1 + (size_t)s0 * 64 + c * 4);
                float4 v1 = *(const float4*)(g_t1 + (size_t)s1 * 64 + c * 4);
                float4 v2 = *(const float4*)(g_t1 + (size_t)s2 * 64 + c * 4);
                float4 v3 = *(const float4*)(g_t1 + (size_t)s3 * 64 + c * 4);
                acc.x += (v0.x + v1.x) + (v2.x + v3.x);
                acc.y += (v0.y + v1.y) + (v2.y + v3.y);
                acc.z += (v0.z + v1.z) + (v2.z + v3.z);
                acc.w += (v0.w + v1.w) + (v2.w + v3.w);
            }
            for (; i < end; i++) {
                int s0 = g_col[i];
                float4 v0 = *(const float4*)(g_t1 + (size_t)s0 * 64 + c * 4);
                acc.x += v0.x; acc.y += v0.y; acc.z += v0.z; acc.w += v0.w;
            }
            float inv = 1.0f / fmaxf((float)(end - start), 1.0f);
            float4 u = *(const float4*)(g_u1 + (size_t)n * 64 + c * 4);
            float4 o;
            o.x = fmaxf(fmaf(acc.x, inv, u.x + bb.x), 0.0f);
            o.y = fmaxf(fmaf(acc.y, inv, u.y + bb.y), 0.0f);
            o.z = fmaxf(fmaf(acc.z, inv, u.z + bb.z), 0.0f);
            o.w = fmaxf(fmaf(acc.w, inv, u.w + bb.w), 0.0f);
            float* d = sH + ln * FP + c * 4;
            d[0] = o.x; d[1] = o.y; d[2] = o.z; d[3] = o.w;
        } else {
            float* d = sH + ln * FP + c * 4;
            d[0] = 0.f; d[1] = 0.f; d[2] = 0.f; d[3] = 0.f;
        }
    }

    // commit weights to smem, then sync once for both sH and sW
    #pragma unroll
    for (int iw = 0; iw < 4; iw++)
        ((float4*)sW)[tid + iw * 256] = wreg[iw];
    __syncthreads();

    // phase 2: per-node GEMM from smem. ln2 = tid>>2 (node), q = tid&3.
    int ln2 = tid >> 2;
    int q   = tid & 3;
    int n   = base + ln2;
    unsigned long long acc[8] = {};
    const float* fp = sH + ln2 * FP;
    const float* wq = sW + (q << 2);

    #pragma unroll 8
    for (int k = 0; k < 64; k++) {
        float f = fp[k];
        unsigned long long fd;
        asm("mov.b64 %0, {%1,%1};" : "=l"(fd) : "f"(f));
        const float* wr = wq + k * 64;
        #pragma unroll
        for (int j8 = 0; j8 < 4; j8++) {
            ulonglong2 w = *(const ulonglong2*)(wr + j8 * 16);
            FMA2(acc[j8 * 2],     fd, w.x);
            FMA2(acc[j8 * 2 + 1], fd, w.y);
        }
    }

    if (n < N_NODES) {
        #pragma unroll
        for (int j8 = 0; j8 < 4; j8++) {
            int jb = j8 * 16 + (q << 2);
            float* dst = (jb < 32) ? g_t2 : g_u2;
            int joff = jb & 31;
            float o[4];
            asm("mov.b64 {%0,%1}, %2;" : "=f"(o[0]), "=f"(o[1]) : "l"(acc[j8 * 2]));
            asm("mov.b64 {%0,%1}, %2;" : "=f"(o[2]), "=f"(o[3]) : "l"(acc[j8 * 2 + 1]));
            *(float4*)(dst + (size_t)n * 32 + joff) = *(float4*)o;
        }
    }
}

// ---------------- layer 2 output: out = mean_gather(t2) + u2 + b2 ----------------
__global__ __launch_bounds__(256)
void agg_final_kernel(const float* __restrict__ b2, float* __restrict__ out) {
    int tid = threadIdx.x;
    int g = tid >> 3;
    int c = tid & 7;
    int n = blockIdx.x * 32 + g;
    if (n >= N_NODES) return;
    int start = g_rowptr[n], end = g_rowptr[n + 1];
    float4 acc = make_float4(0.f, 0.f, 0.f, 0.f);
    int i = start;
    for (; i + 3 < end; i += 4) {
        int s0 = g_col[i], s1 = g_col[i + 1], s2 = g_col[i + 2], s3 = g_col[i + 3];
        float4 v0 = *(const float4*)(g_t2 + (size_t)s0 * 32 + c * 4);
        float4 v1 = *(const float4*)(g_t2 + (size_t)s1 * 32 + c * 4);
        float4 v2 = *(const float4*)(g_t2 + (size_t)s2 * 32 + c * 4);
        float4 v3 = *(const float4*)(g_t2 + (size_t)s3 * 32 + c * 4);
        acc.x += (v0.x + v1.x) + (v2.x + v3.x);
        acc.y += (v0.y + v1.y) + (v2.y + v3.y);
        acc.z += (v0.z + v1.z) + (v2.z + v3.z);
        acc.w += (v0.w + v1.w) + (v2.w + v3.w);
    }
    for (; i < end; i++) {
        int s0 = g_col[i];
        float4 v0 = *(const float4*)(g_t2 + (size_t)s0 * 32 + c * 4);
        acc.x += v0.x; acc.y += v0.y; acc.z += v0.z; acc.w += v0.w;
    }
    float inv = 1.0f / fmaxf((float)(end - start), 1.0f);
    float4 u = *(const float4*)(g_u2 + (size_t)n * 32 + c * 4);
    float4 bb = *(const float4*)(b2 + c * 4);
    float4 o;
    o.x = fmaf(acc.x, inv, u.x + bb.x);
    o.y = fmaf(acc.y, inv, u.y + bb.y);
    o.z = fmaf(acc.z, inv, u.z + bb.z);
    o.w = fmaf(acc.w, inv, u.w + bb.w);
    *(float4*)(out + (size_t)n * 32 + c * 4) = o;
}

// ---------------- launch ----------------
extern "C" void kernel_launch(void* const* d_in, const int* in_sizes, int n_in,
                              void* d_out, int out_size) {
    const float* x   = (const float*)d_in[0];
    const void*  ei  = d_in[1];
    const float* W1n = (const float*)d_in[2];
    const float* W1s = (const float*)d_in[3];
    const float* b1  = (const float*)d_in[4];
    const float* W2n = (const float*)d_in[5];
    const float* W2s = (const float*)d_in[6];
    const float* b2  = (const float*)d_in[7];
    float* out = (float*)d_out;
    int E = in_sizes[1] / 2;

    // Fork a side stream inside capture: CSR build runs concurrently with
    // the layer-1 GEMM (they are independent).
    cudaStream_t s2;
    cudaStreamCreate(&s2);
    cudaEvent_t evFork, evJoin;
    cudaEventCreateWithFlags(&evFork, cudaEventDisableTiming);
    cudaEventCreateWithFlags(&evJoin, cudaEventDisableTiming);

    cudaEventRecord(evFork, 0);          // null (capture) stream
    cudaStreamWaitEvent(s2, evFork, 0);

    // CSR build on side stream
    count_kernel<<<(E / 2 + 256) / 256, 256, 0, s2>>>(ei, E);
    scan1_kernel<<<SCAN_CHUNKS, 1024, 0, s2>>>();
    scan3_kernel<<<SCAN_CHUNKS, 1024, 0, s2>>>();
    fill_kernel<<<(E / 2 + 256) / 256, 256, 0, s2>>>(ei, E);
    cudaEventRecord(evJoin, s2);

    // layer-1 GEMM on main stream, concurrent with CSR build
    gemmA_kernel<<<(N_NODES + 63) / 64, 256>>>(x, W1n, W1s);

    // join: fused layer needs both CSR and t1/u1
    cudaStreamWaitEvent(0, evJoin, 0);

    fusedH_kernel<<<(N_NODES + 63) / 64, 256>>>(b1, W2n, W2s);
    agg_final_kernel<<<(N_NODES + 31) / 32, 256>>>(b2, out);

    cudaEventDestroy(evFork);
    cudaEventDestroy(evJoin);
    cudaStreamDestroy(s2);
}

// round 11
// speedup vs baseline: 1.1556x; 1.1556x over previous
#include <cuda_runtime.h>
#include <cuda_bf16.h>
#include <cstdint>

#define N_NODES 100000
#define N_EDGES 1600000

// ---------------- scratch (device globals; no allocations) ----------------
// g_cnt is zero at process start and re-zeroed by offs_kernel each call.
// g_total is zeroed by count_kernel (thread 0) each call.
__device__ int   g_cnt[N_NODES];                 // degree histogram
__device__ int   g_total;                        // running segment allocator
__device__ int   g_rank[N_EDGES];                // per-edge rank within its dst
__device__ int   g_start[N_NODES];               // segment start per node (unordered)
__device__ int   g_deg[N_NODES];                 // degree per node
__device__ int   g_col[N_EDGES];                 // CSR column (src) indices
__device__ float g_t1[(size_t)N_NODES * 64];     // x @ W1n
__device__ float g_u1[(size_t)N_NODES * 64];     // x @ W1s
__device__ float g_h [(size_t)N_NODES * 64];     // layer-1 output (relu)
__device__ float g_t2[(size_t)N_NODES * 32];     // h @ W2n
__device__ float g_u2[(size_t)N_NODES * 32];     // h @ W2s

// inline edge-width detection: int64 values < 2^31 have zero high words.
__device__ __forceinline__ int detect_is64(const int* ei32) {
    return (ei32[1] == 0 && ei32[3] == 0 && ei32[5] == 0 && ei32[7] == 0) ? 1 : 0;
}

// ---------------- CSR build (3 kernels) ----------------
__global__ void count_kernel(const void* __restrict__ ei, int E) {
    int t = blockIdx.x * blockDim.x + threadIdx.x;
    if (t == 0) g_total = 0;            // reset allocator for offs_kernel
    int e0 = t * 2;
    if (e0 >= E) return;
    int is64 = detect_is64((const int*)ei);
    int d0, d1 = -1;
    if (is64) {
        const long long* p = (const long long*)ei + E;
        d0 = (int)p[e0];
        if (e0 + 1 < E) d1 = (int)p[e0 + 1];
    } else {
        const int* p = (const int*)ei + E;
        d0 = p[e0];
        if (e0 + 1 < E) d1 = p[e0 + 1];
    }
    int r0 = atomicAdd(&g_cnt[d0], 1);
    g_rank[e0] = r0;
    if (d1 >= 0) {
        int r1 = atomicAdd(&g_cnt[d1], 1);
        g_rank[e0 + 1] = r1;
    }
}

// single-pass segment allocation: warp scan + one atomic per block.
// Segments are disjoint but NOT node-ordered (aggs use start+deg, not n+1).
__global__ void offs_kernel() {
    int tid = threadIdx.x;
    int n = blockIdx.x * 256 + tid;
    int lane = tid & 31, wid = tid >> 5;
    int c = (n < N_NODES) ? g_cnt[n] : 0;

    // warp inclusive scan
    int v = c;
    #pragma unroll
    for (int off = 1; off < 32; off <<= 1) {
        int t = __shfl_up_sync(0xffffffffu, v, off);
        if (lane >= off) v += t;
    }
    int excl = v - c;

    __shared__ int woff[8];
    __shared__ int bbase;
    if (lane == 31) woff[wid] = v;      // warp totals
    __syncthreads();
    if (wid == 0) {
        int orig = (lane < 8) ? woff[lane] : 0;
        int wv = orig;
        #pragma unroll
        for (int off = 1; off < 8; off <<= 1) {
            int t = __shfl_up_sync(0xffffffffu, wv, off);
            if (lane >= off) wv += t;
        }
        if (lane == 7) bbase = atomicAdd(&g_total, wv);   // block base
        if (lane < 8) woff[lane] = wv - orig;             // exclusive warp offsets
    }
    __syncthreads();

    if (n < N_NODES) {
        g_start[n] = bbase + woff[wid] + excl;
        g_deg[n]   = c;
        g_cnt[n]   = 0;                 // re-zero for next invocation
    }
}

// fill: pos = start[dst] + rank[e] — no atomics.
__global__ void fill_kernel(const void* __restrict__ ei, int E) {
    int t = blockIdx.x * blockDim.x + threadIdx.x;
    int e0 = t * 2;
    if (e0 >= E) return;
    int is64 = detect_is64((const int*)ei);
    int s0, d0, s1 = -1, d1 = -1;
    if (is64) {
        const long long* p = (const long long*)ei;
        s0 = (int)p[e0]; d0 = (int)p[E + e0];
        if (e0 + 1 < E) { s1 = (int)p[e0 + 1]; d1 = (int)p[E + e0 + 1]; }
    } else {
        const int* p = (const int*)ei;
        s0 = p[e0]; d0 = p[E + e0];
        if (e0 + 1 < E) { s1 = p[e0 + 1]; d1 = p[E + e0 + 1]; }
    }
    int p0 = g_start[d0] + g_rank[e0];
    g_col[p0] = s0;
    if (d1 >= 0) {
        int p1 = g_start[d1] + g_rank[e0 + 1];
        g_col[p1] = s1;
    }
}

// ---------------- pipelined packed-f32x2 dual-output GEMM ----------------
#define FMA2(acc, a2, b2) \
    asm("fma.rn.f32x2 %0, %1, %2, %0;" : "+l"(acc) : "l"(a2), "l"(b2))

template<int OUTT, int LAYER>
__global__ __launch_bounds__(256, 2)
void gemm_dual_kernel(const float* __restrict__ xsrc,
                      const float* __restrict__ Wa,   // [64, OUTT]
                      const float* __restrict__ Wb) { // [64, OUTT]
    constexpr int OUT = 2 * OUTT;          // 128 or 64
    constexpr int TPN = OUT / 16;          // 8 or 4 threads per node
    constexpr int NB  = 8192 / OUT;        // 64 or 128 nodes per block
    constexpr int HALF = NB / 2;
    constexpr int FP  = 33;
    constexpr int NF4 = NB / 32;           // feature float4 per thread (2 or 4)
    constexpr int NW4 = OUT / 32;           // weight float4 per thread (4 or 2)
    constexpr int JQW = OUT / 4;

    const float* src = (LAYER == 1) ? xsrc : g_h;
    float* dstA = (LAYER == 1) ? g_t1 : g_t2;
    float* dstB = (LAYER == 1) ? g_u1 : g_u2;

    __shared__ float sF[NB * FP];
    __shared__ float sW[32 * OUT];

    int tid = threadIdx.x;
    int base = blockIdx.x * NB;
    int ln = tid / TPN;
    int q  = tid % TPN;
    int k4 = tid & 7;

    int r_[NF4], nc_[NF4];
    #pragma unroll
    for (int it = 0; it < NF4; it++) {
        r_[it] = (tid + it * 256) >> 3;
        int n = base + r_[it];
        nc_[it] = (n < N_NODES) ? n : (N_NODES - 1);
    }
    float4 pf[NF4], pw[NW4];

    auto load_chunk = [&](int c) {
        #pragma unroll
        for (int it = 0; it < NF4; it++)
            pf[it] = *(const float4*)(src + (size_t)nc_[it] * 64 + c * 32 + k4 * 4);
        #pragma unroll
        for (int iw = 0; iw < NW4; iw++) {
            int idx = tid + iw * 256;
            int kk = idx / JQW, jq = idx % JQW;
            int k = c * 32 + kk;
            const float* wsrc = (jq < OUTT / 4) ? (Wa + k * OUTT + jq * 4)
                                                : (Wb + k * OUTT + jq * 4 - OUTT);
            pw[iw] = *(const float4*)wsrc;
        }
    };
    auto store_stage = [&]() {
        #pragma unroll
        for (int it = 0; it < NF4; it++) {
            float* d = sF + r_[it] * FP + k4 * 4;
            d[0] = pf[it].x; d[1] = pf[it].y; d[2] = pf[it].z; d[3] = pf[it].w;
        }
        #pragma unroll
        for (int iw = 0; iw < NW4; iw++)
            ((float4*)sW)[tid + iw * 256] = pw[iw];
    };

    load_chunk(0);
    store_stage();
    __syncthreads();

    unsigned long long acc0[8] = {}, acc1[8] = {};
    const float* fp0 = sF + ln * FP;
    const float* fp1 = sF + (ln + HALF) * FP;
    const float* wq  = sW + (q << 2);

    #pragma unroll 1
    for (int c = 0; c < 2; c++) {
        if (c < 1) load_chunk(1);
        #pragma unroll 8
        for (int kk = 0; kk < 32; kk++) {
            float f0 = fp0[kk], f1 = fp1[kk];
            unsigned long long f0d, f1d;
            asm("mov.b64 %0, {%1,%1};" : "=l"(f0d) : "f"(f0));
            asm("mov.b64 %0, {%1,%1};" : "=l"(f1d) : "f"(f1));
            const float* wr = wq + kk * OUT;
            #pragma unroll
            for (int j8 = 0; j8 < 4; j8++) {
                ulonglong2 w = *(const ulonglong2*)(wr + j8 * TPN * 4);
                FMA2(acc0[j8 * 2],     f0d, w.x);
                FMA2(acc0[j8 * 2 + 1], f0d, w.y);
                FMA2(acc1[j8 * 2],     f1d, w.x);
                FMA2(acc1[j8 * 2 + 1], f1d, w.y);
            }
        }
        __syncthreads();
        if (c < 1) { store_stage(); __syncthreads(); }
    }

    int n0 = base + ln, n1 = base + ln + HALF;
    #pragma unroll
    for (int j8 = 0; j8 < 4; j8++) {
        int jb = j8 * TPN * 4 + (q << 2);
        float* dst = (j8 < 2) ? dstA : dstB;
        int joff = (j8 < 2) ? jb : jb - OUTT;
        if (n0 < N_NODES) {
            float o[4];
            asm("mov.b64 {%0,%1}, %2;" : "=f"(o[0]), "=f"(o[1]) : "l"(acc0[j8 * 2]));
            asm("mov.b64 {%0,%1}, %2;" : "=f"(o[2]), "=f"(o[3]) : "l"(acc0[j8 * 2 + 1]));
            *(float4*)(dst + (size_t)n0 * OUTT + joff) = *(float4*)o;
        }
        if (n1 < N_NODES) {
            float o[4];
            asm("mov.b64 {%0,%1}, %2;" : "=f"(o[0]), "=f"(o[1]) : "l"(acc1[j8 * 2]));
            asm("mov.b64 {%0,%1}, %2;" : "=f"(o[2]), "=f"(o[3]) : "l"(acc1[j8 * 2 + 1]));
            *(float4*)(dst + (size_t)n1 * OUTT + joff) = *(float4*)o;
        }
    }
}

// ---------------- gather-mean + epilogue kernels ----------------
// layer 1: h = relu(mean_gather(t1) + u1 + b1); rows 64 wide; 16 lanes/node.
__global__ __launch_bounds__(256)
void aggH_kernel(const float* __restrict__ b1) {
    int tid = threadIdx.x;
    int g = tid >> 4;
    int c = tid & 15;
    int n = blockIdx.x * 16 + g;
    if (n >= N_NODES) return;
    int start = g_start[n], deg = g_deg[n], end = start + deg;
    float4 acc = make_float4(0.f, 0.f, 0.f, 0.f);
    int i = start;
    for (; i + 3 < end; i += 4) {
        int s0 = g_col[i], s1 = g_col[i + 1], s2 = g_col[i + 2], s3 = g_col[i + 3];
        float4 v0 = *(const float4*)(g_t1 + (size_t)s0 * 64 + c * 4);
        float4 v1 = *(const float4*)(g_t1 + (size_t)s1 * 64 + c * 4);
        float4 v2 = *(const float4*)(g_t1 + (size_t)s2 * 64 + c * 4);
        float4 v3 = *(const float4*)(g_t1 + (size_t)s3 * 64 + c * 4);
        acc.x += (v0.x + v1.x) + (v2.x + v3.x);
        acc.y += (v0.y + v1.y) + (v2.y + v3.y);
        acc.z += (v0.z + v1.z) + (v2.z + v3.z);
        acc.w += (v0.w + v1.w) + (v2.w + v3.w);
    }
    for (; i < end; i++) {
        int s0 = g_col[i];
        float4 v0 = *(const float4*)(g_t1 + (size_t)s0 * 64 + c * 4);
        acc.x += v0.x; acc.y += v0.y; acc.z += v0.z; acc.w += v0.w;
    }
    float inv = 1.0f / fmaxf((float)deg, 1.0f);
    float4 u = *(const float4*)(g_u1 + (size_t)n * 64 + c * 4);
    float4 bb = *(const float4*)(b1 + c * 4);
    float4 o;
    o.x = fmaxf(fmaf(acc.x, inv, u.x + bb.x), 0.0f);
    o.y = fmaxf(fmaf(acc.y, inv, u.y + bb.y), 0.0f);
    o.z = fmaxf(fmaf(acc.z, inv, u.z + bb.z), 0.0f);
    o.w = fmaxf(fmaf(acc.w, inv, u.w + bb.w), 0.0f);
    *(float4*)(g_h + (size_t)n * 64 + c * 4) = o;
}

// layer 2: out = mean_gather(t2) + u2 + b2; rows 32 wide; 8 lanes/node.
__global__ __launch_bounds__(256)
void agg_final_kernel(const float* __restrict__ b2, float* __restrict__ out) {
    int tid = threadIdx.x;
    int g = tid >> 3;
    int c = tid & 7;
    int n = blockIdx.x * 32 + g;
    if (n >= N_NODES) return;
    int start = g_start[n], deg = g_deg[n], end = start + deg;
    float4 acc = make_float4(0.f, 0.f, 0.f, 0.f);
    int i = start;
    for (; i + 3 < end; i += 4) {
        int s0 = g_col[i], s1 = g_col[i + 1], s2 = g_col[i + 2], s3 = g_col[i + 3];
        float4 v0 = *(const float4*)(g_t2 + (size_t)s0 * 32 + c * 4);
        float4 v1 = *(const float4*)(g_t2 + (size_t)s1 * 32 + c * 4);
        float4 v2 = *(const float4*)(g_t2 + (size_t)s2 * 32 + c * 4);
        float4 v3 = *(const float4*)(g_t2 + (size_t)s3 * 32 + c * 4);
        acc.x += (v0.x + v1.x) + (v2.x + v3.x);
        acc.y += (v0.y + v1.y) + (v2.y + v3.y);
        acc.z += (v0.z + v1.z) + (v2.z + v3.z);
        acc.w += (v0.w + v1.w) + (v2.w + v3.w);
    }
    for (; i < end; i++) {
        int s0 = g_col[i];
        float4 v0 = *(const float4*)(g_t2 + (size_t)s0 * 32 + c * 4);
        acc.x += v0.x; acc.y += v0.y; acc.z += v0.z; acc.w += v0.w;
    }
    float inv = 1.0f / fmaxf((float)deg, 1.0f);
    float4 u = *(const float4*)(g_u2 + (size_t)n * 32 + c * 4);
    float4 bb = *(const float4*)(b2 + c * 4);
    float4 o;
    o.x = fmaf(acc.x, inv, u.x + bb.x);
    o.y = fmaf(acc.y, inv, u.y + bb.y);
    o.z = fmaf(acc.z, inv, u.z + bb.z);
    o.w = fmaf(acc.w, inv, u.w + bb.w);
    *(float4*)(out + (size_t)n * 32 + c * 4) = o;
}

// ---------------- launch ----------------
extern "C" void kernel_launch(void* const* d_in, const int* in_sizes, int n_in,
                              void* d_out, int out_size) {
    const float* x   = (const float*)d_in[0];
    const void*  ei  = d_in[1];
    const float* W1n = (const float*)d_in[2];
    const float* W1s = (const float*)d_in[3];
    const float* b1  = (const float*)d_in[4];
    const float* W2n = (const float*)d_in[5];
    const float* W2s = (const float*)d_in[6];
    const float* b2  = (const float*)d_in[7];
    float* out = (float*)d_out;
    int E = in_sizes[1] / 2;

    // Fork a side stream inside capture: CSR build runs concurrently with
    // the layer-1 GEMM (they are independent).
    cudaStream_t s2;
    cudaStreamCreate(&s2);
    cudaEvent_t evFork, evJoin;
    cudaEventCreateWithFlags(&evFork, cudaEventDisableTiming);
    cudaEventCreateWithFlags(&evJoin, cudaEventDisableTiming);

    cudaEventRecord(evFork, 0);          // null (capture) stream
    cudaStreamWaitEvent(s2, evFork, 0);

    // CSR build on side stream (3 kernels)
    count_kernel<<<(E / 2 + 256) / 256, 256, 0, s2>>>(ei, E);
    offs_kernel<<<(N_NODES + 255) / 256, 256, 0, s2>>>();
    fill_kernel<<<(E / 2 + 256) / 256, 256, 0, s2>>>(ei, E);
    cudaEventRecord(evJoin, s2);

    // layer-1 GEMM on main stream, concurrent with CSR build
    gemm_dual_kernel<64, 1><<<(N_NODES + 63) / 64, 256>>>(x, W1n, W1s);

    // join: aggregation needs both CSR and t1/u1
    cudaStreamWaitEvent(0, evJoin, 0);

    aggH_kernel<<<(N_NODES + 15) / 16, 256>>>(b1);
    gemm_dual_kernel<32, 2><<<(N_NODES + 127) / 128, 256>>>(nullptr, W2n, W2s);
    agg_final_kernel<<<(N_NODES + 31) / 32, 256>>>(b2, out);

    cudaEventDestroy(evFork);
    cudaEventDestroy(evJoin);
    cudaStreamDestroy(s2);
}

// round 12
// speedup vs baseline: 1.2765x; 1.1046x over previous
#include <cuda_runtime.h>
#include <cuda_bf16.h>
#include <cstdint>

#define N_NODES 100000
#define N_EDGES 1600000

// ---------------- scratch (device globals; no allocations) ----------------
// g_cnt is zero at process start and re-zeroed by offs_kernel each call.
// g_total is zeroed by count_kernel (thread 0) each call.
__device__ int   g_cnt[N_NODES];                 // degree histogram
__device__ int   g_total;                        // running segment allocator
__device__ int   g_rank[N_EDGES];                // per-edge rank within its dst
__device__ int   g_start[N_NODES];               // segment start per node (unordered)
__device__ int   g_deg[N_NODES];                 // degree per node
__device__ int   g_col[N_EDGES];                 // CSR column (src) indices
__device__ float g_t1[(size_t)N_NODES * 64];     // x @ W1n
__device__ float g_u1[(size_t)N_NODES * 64];     // x @ W1s
__device__ float g_h [(size_t)N_NODES * 64];     // layer-1 output (relu)
__device__ float g_t2[(size_t)N_NODES * 32];     // h @ W2n
__device__ float g_u2[(size_t)N_NODES * 32];     // h @ W2s

// inline edge-width detection: int64 values < 2^31 have zero high words.
__device__ __forceinline__ int detect_is64(const int* ei32) {
    return (ei32[1] == 0 && ei32[3] == 0 && ei32[5] == 0 && ei32[7] == 0) ? 1 : 0;
}

// ---------------- CSR build (3 kernels) ----------------
__global__ void count_kernel(const void* __restrict__ ei, int E) {
    int t = blockIdx.x * blockDim.x + threadIdx.x;
    if (t == 0) g_total = 0;            // reset allocator for offs_kernel
    int e0 = t * 2;
    if (e0 >= E) return;
    int is64 = detect_is64((const int*)ei);
    int d0, d1 = -1;
    if (is64) {
        const long long* p = (const long long*)ei + E;
        d0 = (int)p[e0];
        if (e0 + 1 < E) d1 = (int)p[e0 + 1];
    } else {
        const int* p = (const int*)ei + E;
        d0 = p[e0];
        if (e0 + 1 < E) d1 = p[e0 + 1];
    }
    int r0 = atomicAdd(&g_cnt[d0], 1);
    g_rank[e0] = r0;
    if (d1 >= 0) {
        int r1 = atomicAdd(&g_cnt[d1], 1);
        g_rank[e0 + 1] = r1;
    }
}

// single-pass segment allocation: warp scan + one atomic per block.
// Segments are disjoint but NOT node-ordered (aggs use start+deg).
__global__ void offs_kernel() {
    int tid = threadIdx.x;
    int n = blockIdx.x * 256 + tid;
    int lane = tid & 31, wid = tid >> 5;
    int c = (n < N_NODES) ? g_cnt[n] : 0;

    int v = c;
    #pragma unroll
    for (int off = 1; off < 32; off <<= 1) {
        int t = __shfl_up_sync(0xffffffffu, v, off);
        if (lane >= off) v += t;
    }
    int excl = v - c;

    __shared__ int woff[8];
    __shared__ int bbase;
    if (lane == 31) woff[wid] = v;
    __syncthreads();
    if (wid == 0) {
        int orig = (lane < 8) ? woff[lane] : 0;
        int wv = orig;
        #pragma unroll
        for (int off = 1; off < 8; off <<= 1) {
            int t = __shfl_up_sync(0xffffffffu, wv, off);
            if (lane >= off) wv += t;
        }
        if (lane == 7) bbase = atomicAdd(&g_total, wv);
        if (lane < 8) woff[lane] = wv - orig;
    }
    __syncthreads();

    if (n < N_NODES) {
        g_start[n] = bbase + woff[wid] + excl;
        g_deg[n]   = c;
        g_cnt[n]   = 0;
    }
}

// fill: pos = start[dst] + rank[e] — no atomics.
__global__ void fill_kernel(const void* __restrict__ ei, int E) {
    int t = blockIdx.x * blockDim.x + threadIdx.x;
    int e0 = t * 2;
    if (e0 >= E) return;
    int is64 = detect_is64((const int*)ei);
    int s0, d0, s1 = -1, d1 = -1;
    if (is64) {
        const long long* p = (const long long*)ei;
        s0 = (int)p[e0]; d0 = (int)p[E + e0];
        if (e0 + 1 < E) { s1 = (int)p[e0 + 1]; d1 = (int)p[E + e0 + 1]; }
    } else {
        const int* p = (const int*)ei;
        s0 = p[e0]; d0 = p[E + e0];
        if (e0 + 1 < E) { s1 = p[e0 + 1]; d1 = p[E + e0 + 1]; }
    }
    int p0 = g_start[d0] + g_rank[e0];
    g_col[p0] = s0;
    if (d1 >= 0) {
        int p1 = g_start[d1] + g_rank[e0 + 1];
        g_col[p1] = s1;
    }
}

#define FMA2(acc, a2, b2) \
    asm("fma.rn.f32x2 %0, %1, %2, %0;" : "+l"(acc) : "l"(a2), "l"(b2))

// ---------------- layer-1 GEMM: [t1|u1] = x @ [W1n|W1s] ----------------
// 4 nodes x 16 outputs per thread (crossbar demand halved vs 2-node).
// 256 threads, NB=128 nodes/block, TPN=8. ln = tid>>3 (0..31), nodes
// ln, ln+32, ln+64, ln+96. Outputs j = j8*32 + q*4 + 0..3.
__global__ __launch_bounds__(256, 2)
void gemmA_kernel(const float* __restrict__ src,
                  const float* __restrict__ Wa,   // [64, 64] = W1n
                  const float* __restrict__ Wb) { // [64, 64] = W1s
    constexpr int FP = 33;
    __shared__ float sF[128 * FP];      // 16.9KB
    __shared__ float sW[32 * 128];      // 16KB per chunk

    int tid = threadIdx.x;
    int base = blockIdx.x * 128;
    int ln = tid >> 3;                  // 0..31
    int q  = tid & 7;                   // 0..7
    int k4 = tid & 7;

    int r_[4], nc_[4];
    #pragma unroll
    for (int it = 0; it < 4; it++) {
        r_[it] = (tid + it * 256) >> 3;        // 0..127
        int n = base + r_[it];
        nc_[it] = (n < N_NODES) ? n : (N_NODES - 1);
    }
    float4 pf[4], pw[4];

    auto load_chunk = [&](int c) {
        #pragma unroll
        for (int it = 0; it < 4; it++)
            pf[it] = *(const float4*)(src + (size_t)nc_[it] * 64 + c * 32 + k4 * 4);
        #pragma unroll
        for (int iw = 0; iw < 4; iw++) {
            int idx = tid + iw * 256;
            int kk = idx >> 5, jq = idx & 31;
            int k = c * 32 + kk;
            const float* wsrc = (jq < 16) ? (Wa + k * 64 + jq * 4)
                                          : (Wb + k * 64 + jq * 4 - 64);
            pw[iw] = *(const float4*)wsrc;
        }
    };
    auto store_stage = [&]() {
        #pragma unroll
        for (int it = 0; it < 4; it++) {
            float* d = sF + r_[it] * FP + k4 * 4;
            d[0] = pf[it].x; d[1] = pf[it].y; d[2] = pf[it].z; d[3] = pf[it].w;
        }
        #pragma unroll
        for (int iw = 0; iw < 4; iw++)
            ((float4*)sW)[tid + iw * 256] = pw[iw];
    };

    load_chunk(0);
    store_stage();
    __syncthreads();

    unsigned long long acc[4][8];       // [node][j8*2 + hi/lo]
    #pragma unroll
    for (int i = 0; i < 4; i++)
        #pragma unroll
        for (int j = 0; j < 8; j++) acc[i][j] = 0ULL;

    const float* wq = sW + (q << 2);

    #pragma unroll 1
    for (int c = 0; c < 2; c++) {
        if (c < 1) load_chunk(1);
        #pragma unroll 4
        for (int kk = 0; kk < 32; kk++) {
            unsigned long long fd[4];
            #pragma unroll
            for (int i = 0; i < 4; i++) {
                float f = sF[(ln + i * 32) * FP + kk];
                asm("mov.b64 %0, {%1,%1};" : "=l"(fd[i]) : "f"(f));
            }
            const float* wr = wq + kk * 128;
            #pragma unroll
            for (int j8 = 0; j8 < 4; j8++) {
                ulonglong2 w = *(const ulonglong2*)(wr + j8 * 32);
                #pragma unroll
                for (int i = 0; i < 4; i++) {
                    FMA2(acc[i][j8 * 2],     fd[i], w.x);
                    FMA2(acc[i][j8 * 2 + 1], fd[i], w.y);
                }
            }
        }
        __syncthreads();
        if (c < 1) { store_stage(); __syncthreads(); }
    }

    #pragma unroll
    for (int i = 0; i < 4; i++) {
        int n = base + ln + i * 32;
        if (n >= N_NODES) continue;
        #pragma unroll
        for (int j8 = 0; j8 < 4; j8++) {
            int jb = j8 * 32 + (q << 2);
            float* dst = (jb < 64) ? g_t1 : g_u1;
            int joff = jb & 63;
            float o[4];
            asm("mov.b64 {%0,%1}, %2;" : "=f"(o[0]), "=f"(o[1]) : "l"(acc[i][j8 * 2]));
            asm("mov.b64 {%0,%1}, %2;" : "=f"(o[2]), "=f"(o[3]) : "l"(acc[i][j8 * 2 + 1]));
            *(float4*)(dst + (size_t)n * 64 + joff) = *(float4*)o;
        }
    }
}

// ---------------- layer-2 GEMM: [t2|u2] = h @ [W2n|W2s] (2-node version) ----------------
__global__ __launch_bounds__(256, 2)
void gemmD_kernel(const float* __restrict__ Wa,   // [64, 32] = W2n
                  const float* __restrict__ Wb) { // [64, 32] = W2s
    constexpr int OUT = 64, TPN = 4, NB = 128, HALF = 64, FP = 33;
    const float* src = g_h;
    __shared__ float sF[NB * FP];
    __shared__ float sW[32 * OUT];

    int tid = threadIdx.x;
    int base = blockIdx.x * NB;
    int ln = tid / TPN;
    int q  = tid % TPN;
    int k4 = tid & 7;

    int r_[4], nc_[4];
    #pragma unroll
    for (int it = 0; it < 4; it++) {
        r_[it] = (tid + it * 256) >> 3;
        int n = base + r_[it];
        nc_[it] = (n < N_NODES) ? n : (N_NODES - 1);
    }
    float4 pf[4], pw[2];

    auto load_chunk = [&](int c) {
        #pragma unroll
        for (int it = 0; it < 4; it++)
            pf[it] = *(const float4*)(src + (size_t)nc_[it] * 64 + c * 32 + k4 * 4);
        #pragma unroll
        for (int iw = 0; iw < 2; iw++) {
            int idx = tid + iw * 256;
            int kk = idx >> 4, jq = idx & 15;
            int k = c * 32 + kk;
            const float* wsrc = (jq < 8) ? (Wa + k * 32 + jq * 4)
                                         : (Wb + k * 32 + jq * 4 - 32);
            pw[iw] = *(const float4*)wsrc;
        }
    };
    auto store_stage = [&]() {
        #pragma unroll
        for (int it = 0; it < 4; it++) {
            float* d = sF + r_[it] * FP + k4 * 4;
            d[0] = pf[it].x; d[1] = pf[it].y; d[2] = pf[it].z; d[3] = pf[it].w;
        }
        #pragma unroll
        for (int iw = 0; iw < 2; iw++)
            ((float4*)sW)[tid + iw * 256] = pw[iw];
    };

    load_chunk(0);
    store_stage();
    __syncthreads();

    unsigned long long acc0[8] = {}, acc1[8] = {};
    const float* fp0 = sF + ln * FP;
    const float* fp1 = sF + (ln + HALF) * FP;
    const float* wq  = sW + (q << 2);

    #pragma unroll 1
    for (int c = 0; c < 2; c++) {
        if (c < 1) load_chunk(1);
        #pragma unroll 8
        for (int kk = 0; kk < 32; kk++) {
            float f0 = fp0[kk], f1 = fp1[kk];
            unsigned long long f0d, f1d;
            asm("mov.b64 %0, {%1,%1};" : "=l"(f0d) : "f"(f0));
            asm("mov.b64 %0, {%1,%1};" : "=l"(f1d) : "f"(f1));
            const float* wr = wq + kk * OUT;
            #pragma unroll
            for (int j8 = 0; j8 < 4; j8++) {
                ulonglong2 w = *(const ulonglong2*)(wr + j8 * 16);
                FMA2(acc0[j8 * 2],     f0d, w.x);
                FMA2(acc0[j8 * 2 + 1], f0d, w.y);
                FMA2(acc1[j8 * 2],     f1d, w.x);
                FMA2(acc1[j8 * 2 + 1], f1d, w.y);
            }
        }
        __syncthreads();
        if (c < 1) { store_stage(); __syncthreads(); }
    }

    int n0 = base + ln, n1 = base + ln + HALF;
    #pragma unroll
    for (int j8 = 0; j8 < 4; j8++) {
        int jb = j8 * 16 + (q << 2);
        float* dst = (jb < 32) ? g_t2 : g_u2;
        int joff = jb & 31;
        if (n0 < N_NODES) {
            float o[4];
            asm("mov.b64 {%0,%1}, %2;" : "=f"(o[0]), "=f"(o[1]) : "l"(acc0[j8 * 2]));
            asm("mov.b64 {%0,%1}, %2;" : "=f"(o[2]), "=f"(o[3]) : "l"(acc0[j8 * 2 + 1]));
            *(float4*)(dst + (size_t)n0 * 32 + joff) = *(float4*)o;
        }
        if (n1 < N_NODES) {
            float o[4];
            asm("mov.b64 {%0,%1}, %2;" : "=f"(o[0]), "=f"(o[1]) : "l"(acc1[j8 * 2]));
            asm("mov.b64 {%0,%1}, %2;" : "=f"(o[2]), "=f"(o[3]) : "l"(acc1[j8 * 2 + 1]));
            *(float4*)(dst + (size_t)n1 * 32 + joff) = *(float4*)o;
        }
    }
}

// ---------------- gather-mean + epilogue kernels ----------------
__global__ __launch_bounds__(256)
void aggH_kernel(const float* __restrict__ b1) {
    int tid = threadIdx.x;
    int g = tid >> 4;
    int c = tid & 15;
    int n = blockIdx.x * 16 + g;
    if (n >= N_NODES) return;
    int start = g_start[n], deg = g_deg[n], end = start + deg;
    float4 acc = make_float4(0.f, 0.f, 0.f, 0.f);
    int i = start;
    for (; i + 3 < end; i += 4) {
        int s0 = g_col[i], s1 = g_col[i + 1], s2 = g_col[i + 2], s3 = g_col[i + 3];
        float4 v0 = *(const float4*)(g_t1 + (size_t)s0 * 64 + c * 4);
        float4 v1 = *(const float4*)(g_t1 + (size_t)s1 * 64 + c * 4);
        float4 v2 = *(const float4*)(g_t1 + (size_t)s2 * 64 + c * 4);
        float4 v3 = *(const float4*)(g_t1 + (size_t)s3 * 64 + c * 4);
        acc.x += (v0.x + v1.x) + (v2.x + v3.x);
        acc.y += (v0.y + v1.y) + (v2.y + v3.y);
        acc.z += (v0.z + v1.z) + (v2.z + v3.z);
        acc.w += (v0.w + v1.w) + (v2.w + v3.w);
    }
    for (; i < end; i++) {
        int s0 = g_col[i];
        float4 v0 = *(const float4*)(g_t1 + (size_t)s0 * 64 + c * 4);
        acc.x += v0.x; acc.y += v0.y; acc.z += v0.z; acc.w += v0.w;
    }
    float inv = 1.0f / fmaxf((float)deg, 1.0f);
    float4 u = *(const float4*)(g_u1 + (size_t)n * 64 + c * 4);
    float4 bb = *(const float4*)(b1 + c * 4);
    float4 o;
    o.x = fmaxf(fmaf(acc.x, inv, u.x + bb.x), 0.0f);
    o.y = fmaxf(fmaf(acc.y, inv, u.y + bb.y), 0.0f);
    o.z = fmaxf(fmaf(acc.z, inv, u.z + bb.z), 0.0f);
    o.w = fmaxf(fmaf(acc.w, inv, u.w + bb.w), 0.0f);
    *(float4*)(g_h + (size_t)n * 64 + c * 4) = o;
}

__global__ __launch_bounds__(256)
void agg_final_kernel(const float* __restrict__ b2, float* __restrict__ out) {
    int tid = threadIdx.x;
    int g = tid >> 3;
    int c = tid & 7;
    int n = blockIdx.x * 32 + g;
    if (n >= N_NODES) return;
    int start = g_start[n], deg = g_deg[n], end = start + deg;
    float4 acc = make_float4(0.f, 0.f, 0.f, 0.f);
    int i = start;
    for (; i + 3 < end; i += 4) {
        int s0 = g_col[i], s1 = g_col[i + 1], s2 = g_col[i + 2], s3 = g_col[i + 3];
        float4 v0 = *(const float4*)(g_t2 + (size_t)s0 * 32 + c * 4);
        float4 v1 = *(const float4*)(g_t2 + (size_t)s1 * 32 + c * 4);
        float4 v2 = *(const float4*)(g_t2 + (size_t)s2 * 32 + c * 4);
        float4 v3 = *(const float4*)(g_t2 + (size_t)s3 * 32 + c * 4);
        acc.x += (v0.x + v1.x) + (v2.x + v3.x);
        acc.y += (v0.y + v1.y) + (v2.y + v3.y);
        acc.z += (v0.z + v1.z) + (v2.z + v3.z);
        acc.w += (v0.w + v1.w) + (v2.w + v3.w);
    }
    for (; i < end; i++) {
        int s0 = g_col[i];
        float4 v0 = *(const float4*)(g_t2 + (size_t)s0 * 32 + c * 4);
        acc.x += v0.x; acc.y += v0.y; acc.z += v0.z; acc.w += v0.w;
    }
    float inv = 1.0f / fmaxf((float)deg, 1.0f);
    float4 u = *(const float4*)(g_u2 + (size_t)n * 32 + c * 4);
    float4 bb = *(const float4*)(b2 + c * 4);
    float4 o;
    o.x = fmaf(acc.x, inv, u.x + bb.x);
    o.y = fmaf(acc.y, inv, u.y + bb.y);
    o.z = fmaf(acc.z, inv, u.z + bb.z);
    o.w = fmaf(acc.w, inv, u.w + bb.w);
    *(float4*)(out + (size_t)n * 32 + c * 4) = o;
}

// ---------------- launch ----------------
extern "C" void kernel_launch(void* const* d_in, const int* in_sizes, int n_in,
                              void* d_out, int out_size) {
    const float* x   = (const float*)d_in[0];
    const void*  ei  = d_in[1];
    const float* W1n = (const float*)d_in[2];
    const float* W1s = (const float*)d_in[3];
    const float* b1  = (const float*)d_in[4];
    const float* W2n = (const float*)d_in[5];
    const float* W2s = (const float*)d_in[6];
    const float* b2  = (const float*)d_in[7];
    float* out = (float*)d_out;
    int E = in_sizes[1] / 2;

    // Fork a side stream inside capture: CSR build runs concurrently with
    // the layer-1 GEMM (they are independent).
    cudaStream_t s2;
    cudaStreamCreate(&s2);
    cudaEvent_t evFork, evJoin;
    cudaEventCreateWithFlags(&evFork, cudaEventDisableTiming);
    cudaEventCreateWithFlags(&evJoin, cudaEventDisableTiming);

    cudaEventRecord(evFork, 0);          // null (capture) stream
    cudaStreamWaitEvent(s2, evFork, 0);

    // CSR build on side stream (3 kernels)
    count_kernel<<<(E / 2 + 256) / 256, 256, 0, s2>>>(ei, E);
    offs_kernel<<<(N_NODES + 255) / 256, 256, 0, s2>>>();
    fill_kernel<<<(E / 2 + 256) / 256, 256, 0, s2>>>(ei, E);
    cudaEventRecord(evJoin, s2);

    // layer-1 GEMM on main stream, concurrent with CSR build
    gemmA_kernel<<<(N_NODES + 127) / 128, 256>>>(x, W1n, W1s);

    // join: aggregation needs both CSR and t1/u1
    cudaStreamWaitEvent(0, evJoin, 0);

    aggH_kernel<<<(N_NODES + 15) / 16, 256>>>(b1);
    gemmD_kernel<<<(N_NODES + 127) / 128, 256>>>(W2n, W2s);
    agg_final_kernel<<<(N_NODES + 31) / 32, 256>>>(b2, out);

    cudaEventDestroy(evFork);
    cudaEventDestroy(evJoin);
    cudaStreamDestroy(s2);
}

// round 13
// speedup vs baseline: 1.3393x; 1.0492x over previous
#include <cuda_runtime.h>
#include <cuda_bf16.h>
#include <cuda_fp16.h>
#include <cstdint>

#define N_NODES 100000
#define N_EDGES 1600000

// ---------------- scratch (device globals; no allocations) ----------------
__device__ int    g_cnt[N_NODES];                 // degree histogram
__device__ int    g_total;                        // running segment allocator
__device__ int    g_rank[N_EDGES];                // per-edge rank within its dst
__device__ int    g_start[N_NODES];               // segment start per node
__device__ int    g_deg[N_NODES];                 // degree per node
__device__ int    g_col[N_EDGES];                 // CSR column (src) indices
__device__ __half g_t1h[(size_t)N_NODES * 64];    // x @ W1n   (fp16, gathered)
__device__ float  g_u1[(size_t)N_NODES * 64];     // x @ W1s   (fp32, sequential)
__device__ float  g_h [(size_t)N_NODES * 64];     // layer-1 output (relu)
__device__ __half g_t2h[(size_t)N_NODES * 32];    // h @ W2n   (fp16, gathered)
__device__ float  g_u2[(size_t)N_NODES * 32];     // h @ W2s   (fp32, sequential)

__device__ __forceinline__ int detect_is64(const int* ei32) {
    return (ei32[1] == 0 && ei32[3] == 0 && ei32[5] == 0 && ei32[7] == 0) ? 1 : 0;
}

// pack 4 floats -> 4 halves (8 bytes)
__device__ __forceinline__ uint2 pack_h4(float a, float b, float c, float d) {
    __half2 lo = __floats2half2_rn(a, b);
    __half2 hi = __floats2half2_rn(c, d);
    uint2 r;
    r.x = *reinterpret_cast<unsigned*>(&lo);
    r.y = *reinterpret_cast<unsigned*>(&hi);
    return r;
}
// unpack 4 halves -> float4
__device__ __forceinline__ float4 unpack_h4(uint2 v) {
    float2 lo = __half22float2(*reinterpret_cast<__half2*>(&v.x));
    float2 hi = __half22float2(*reinterpret_cast<__half2*>(&v.y));
    return make_float4(lo.x, lo.y, hi.x, hi.y);
}

// ---------------- CSR build (3 kernels) ----------------
__global__ void count_kernel(const void* __restrict__ ei, int E) {
    int t = blockIdx.x * blockDim.x + threadIdx.x;
    if (t == 0) g_total = 0;
    int e0 = t * 2;
    if (e0 >= E) return;
    int is64 = detect_is64((const int*)ei);
    int d0, d1 = -1;
    if (is64) {
        const long long* p = (const long long*)ei + E;
        d0 = (int)p[e0];
        if (e0 + 1 < E) d1 = (int)p[e0 + 1];
    } else {
        const int* p = (const int*)ei + E;
        d0 = p[e0];
        if (e0 + 1 < E) d1 = p[e0 + 1];
    }
    int r0 = atomicAdd(&g_cnt[d0], 1);
    g_rank[e0] = r0;
    if (d1 >= 0) {
        int r1 = atomicAdd(&g_cnt[d1], 1);
        g_rank[e0 + 1] = r1;
    }
}

__global__ void offs_kernel() {
    int tid = threadIdx.x;
    int n = blockIdx.x * 256 + tid;
    int lane = tid & 31, wid = tid >> 5;
    int c = (n < N_NODES) ? g_cnt[n] : 0;

    int v = c;
    #pragma unroll
    for (int off = 1; off < 32; off <<= 1) {
        int t = __shfl_up_sync(0xffffffffu, v, off);
        if (lane >= off) v += t;
    }
    int excl = v - c;

    __shared__ int woff[8];
    __shared__ int bbase;
    if (lane == 31) woff[wid] = v;
    __syncthreads();
    if (wid == 0) {
        int orig = (lane < 8) ? woff[lane] : 0;
        int wv = orig;
        #pragma unroll
        for (int off = 1; off < 8; off <<= 1) {
            int t = __shfl_up_sync(0xffffffffu, wv, off);
            if (lane >= off) wv += t;
        }
        if (lane == 7) bbase = atomicAdd(&g_total, wv);
        if (lane < 8) woff[lane] = wv - orig;
    }
    __syncthreads();

    if (n < N_NODES) {
        g_start[n] = bbase + woff[wid] + excl;
        g_deg[n]   = c;
        g_cnt[n]   = 0;
    }
}

__global__ void fill_kernel(const void* __restrict__ ei, int E) {
    int t = blockIdx.x * blockDim.x + threadIdx.x;
    int e0 = t * 2;
    if (e0 >= E) return;
    int is64 = detect_is64((const int*)ei);
    int s0, d0, s1 = -1, d1 = -1;
    if (is64) {
        const long long* p = (const long long*)ei;
        s0 = (int)p[e0]; d0 = (int)p[E + e0];
        if (e0 + 1 < E) { s1 = (int)p[e0 + 1]; d1 = (int)p[E + e0 + 1]; }
    } else {
        const int* p = (const int*)ei;
        s0 = p[e0]; d0 = p[E + e0];
        if (e0 + 1 < E) { s1 = p[e0 + 1]; d1 = p[E + e0 + 1]; }
    }
    int p0 = g_start[d0] + g_rank[e0];
    g_col[p0] = s0;
    if (d1 >= 0) {
        int p1 = g_start[d1] + g_rank[e0 + 1];
        g_col[p1] = s1;
    }
}

#define FMA2(acc, a2, b2) \
    asm("fma.rn.f32x2 %0, %1, %2, %0;" : "+l"(acc) : "l"(a2), "l"(b2))

// ---------------- layer-1 GEMM: t1(h16)=x@W1n, u1(f32)=x@W1s ----------------
// 4 nodes x 16 outputs per thread.
__global__ __launch_bounds__(256, 2)
void gemmA_kernel(const float* __restrict__ src,
                  const float* __restrict__ Wa,   // [64, 64] = W1n
                  const float* __restrict__ Wb) { // [64, 64] = W1s
    constexpr int FP = 33;
    __shared__ float sF[128 * FP];
    __shared__ float sW[32 * 128];

    int tid = threadIdx.x;
    int base = blockIdx.x * 128;
    int ln = tid >> 3;
    int q  = tid & 7;
    int k4 = tid & 7;

    int r_[4], nc_[4];
    #pragma unroll
    for (int it = 0; it < 4; it++) {
        r_[it] = (tid + it * 256) >> 3;
        int n = base + r_[it];
        nc_[it] = (n < N_NODES) ? n : (N_NODES - 1);
    }
    float4 pf[4], pw[4];

    auto load_chunk = [&](int c) {
        #pragma unroll
        for (int it = 0; it < 4; it++)
            pf[it] = *(const float4*)(src + (size_t)nc_[it] * 64 + c * 32 + k4 * 4);
        #pragma unroll
        for (int iw = 0; iw < 4; iw++) {
            int idx = tid + iw * 256;
            int kk = idx >> 5, jq = idx & 31;
            int k = c * 32 + kk;
            const float* wsrc = (jq < 16) ? (Wa + k * 64 + jq * 4)
                                          : (Wb + k * 64 + jq * 4 - 64);
            pw[iw] = *(const float4*)wsrc;
        }
    };
    auto store_stage = [&]() {
        #pragma unroll
        for (int it = 0; it < 4; it++) {
            float* d = sF + r_[it] * FP + k4 * 4;
            d[0] = pf[it].x; d[1] = pf[it].y; d[2] = pf[it].z; d[3] = pf[it].w;
        }
        #pragma unroll
        for (int iw = 0; iw < 4; iw++)
            ((float4*)sW)[tid + iw * 256] = pw[iw];
    };

    load_chunk(0);
    store_stage();
    __syncthreads();

    unsigned long long acc[4][8];
    #pragma unroll
    for (int i = 0; i < 4; i++)
        #pragma unroll
        for (int j = 0; j < 8; j++) acc[i][j] = 0ULL;

    const float* wq = sW + (q << 2);

    #pragma unroll 1
    for (int c = 0; c < 2; c++) {
        if (c < 1) load_chunk(1);
        #pragma unroll 4
        for (int kk = 0; kk < 32; kk++) {
            unsigned long long fd[4];
            #pragma unroll
            for (int i = 0; i < 4; i++) {
                float f = sF[(ln + i * 32) * FP + kk];
                asm("mov.b64 %0, {%1,%1};" : "=l"(fd[i]) : "f"(f));
            }
            const float* wr = wq + kk * 128;
            #pragma unroll
            for (int j8 = 0; j8 < 4; j8++) {
                ulonglong2 w = *(const ulonglong2*)(wr + j8 * 32);
                #pragma unroll
                for (int i = 0; i < 4; i++) {
                    FMA2(acc[i][j8 * 2],     fd[i], w.x);
                    FMA2(acc[i][j8 * 2 + 1], fd[i], w.y);
                }
            }
        }
        __syncthreads();
        if (c < 1) { store_stage(); __syncthreads(); }
    }

    #pragma unroll
    for (int i = 0; i < 4; i++) {
        int n = base + ln + i * 32;
        if (n >= N_NODES) continue;
        #pragma unroll
        for (int j8 = 0; j8 < 4; j8++) {
            int jb = j8 * 32 + (q << 2);
            float o[4];
            asm("mov.b64 {%0,%1}, %2;" : "=f"(o[0]), "=f"(o[1]) : "l"(acc[i][j8 * 2]));
            asm("mov.b64 {%0,%1}, %2;" : "=f"(o[2]), "=f"(o[3]) : "l"(acc[i][j8 * 2 + 1]));
            if (jb < 64) {
                // t1: fp16 (gathered later)
                *(uint2*)(g_t1h + (size_t)n * 64 + jb) = pack_h4(o[0], o[1], o[2], o[3]);
            } else {
                *(float4*)(g_u1 + (size_t)n * 64 + (jb - 64)) = *(float4*)o;
            }
        }
    }
}

// ---------------- layer-2 GEMM: t2(h16)=h@W2n, u2(f32)=h@W2s ----------------
__global__ __launch_bounds__(256, 2)
void gemmD_kernel(const float* __restrict__ Wa,   // [64, 32] = W2n
                  const float* __restrict__ Wb) { // [64, 32] = W2s
    constexpr int OUT = 64, TPN = 4, NB = 128, HALF = 64, FP = 33;
    const float* src = g_h;
    __shared__ float sF[NB * FP];
    __shared__ float sW[32 * OUT];

    int tid = threadIdx.x;
    int base = blockIdx.x * NB;
    int ln = tid / TPN;
    int q  = tid % TPN;
    int k4 = tid & 7;

    int r_[4], nc_[4];
    #pragma unroll
    for (int it = 0; it < 4; it++) {
        r_[it] = (tid + it * 256) >> 3;
        int n = base + r_[it];
        nc_[it] = (n < N_NODES) ? n : (N_NODES - 1);
    }
    float4 pf[4], pw[2];

    auto load_chunk = [&](int c) {
        #pragma unroll
        for (int it = 0; it < 4; it++)
            pf[it] = *(const float4*)(src + (size_t)nc_[it] * 64 + c * 32 + k4 * 4);
        #pragma unroll
        for (int iw = 0; iw < 2; iw++) {
            int idx = tid + iw * 256;
            int kk = idx >> 4, jq = idx & 15;
            int k = c * 32 + kk;
            const float* wsrc = (jq < 8) ? (Wa + k * 32 + jq * 4)
                                         : (Wb + k * 32 + jq * 4 - 32);
            pw[iw] = *(const float4*)wsrc;
        }
    };
    auto store_stage = [&]() {
        #pragma unroll
        for (int it = 0; it < 4; it++) {
            float* d = sF + r_[it] * FP + k4 * 4;
            d[0] = pf[it].x; d[1] = pf[it].y; d[2] = pf[it].z; d[3] = pf[it].w;
        }
        #pragma unroll
        for (int iw = 0; iw < 2; iw++)
            ((float4*)sW)[tid + iw * 256] = pw[iw];
    };

    load_chunk(0);
    store_stage();
    __syncthreads();

    unsigned long long acc0[8] = {}, acc1[8] = {};
    const float* fp0 = sF + ln * FP;
    const float* fp1 = sF + (ln + HALF) * FP;
    const float* wq  = sW + (q << 2);

    #pragma unroll 1
    for (int c = 0; c < 2; c++) {
        if (c < 1) load_chunk(1);
        #pragma unroll 8
        for (int kk = 0; kk < 32; kk++) {
            float f0 = fp0[kk], f1 = fp1[kk];
            unsigned long long f0d, f1d;
            asm("mov.b64 %0, {%1,%1};" : "=l"(f0d) : "f"(f0));
            asm("mov.b64 %0, {%1,%1};" : "=l"(f1d) : "f"(f1));
            const float* wr = wq + kk * OUT;
            #pragma unroll
            for (int j8 = 0; j8 < 4; j8++) {
                ulonglong2 w = *(const ulonglong2*)(wr + j8 * 16);
                FMA2(acc0[j8 * 2],     f0d, w.x);
                FMA2(acc0[j8 * 2 + 1], f0d, w.y);
                FMA2(acc1[j8 * 2],     f1d, w.x);
                FMA2(acc1[j8 * 2 + 1], f1d, w.y);
            }
        }
        __syncthreads();
        if (c < 1) { store_stage(); __syncthreads(); }
    }

    int n0 = base + ln, n1 = base + ln + HALF;
    #pragma unroll
    for (int j8 = 0; j8 < 4; j8++) {
        int jb = j8 * 16 + (q << 2);
        if (n0 < N_NODES) {
            float o[4];
            asm("mov.b64 {%0,%1}, %2;" : "=f"(o[0]), "=f"(o[1]) : "l"(acc0[j8 * 2]));
            asm("mov.b64 {%0,%1}, %2;" : "=f"(o[2]), "=f"(o[3]) : "l"(acc0[j8 * 2 + 1]));
            if (jb < 32)
                *(uint2*)(g_t2h + (size_t)n0 * 32 + jb) = pack_h4(o[0], o[1], o[2], o[3]);
            else
                *(float4*)(g_u2 + (size_t)n0 * 32 + (jb - 32)) = *(float4*)o;
        }
        if (n1 < N_NODES) {
            float o[4];
            asm("mov.b64 {%0,%1}, %2;" : "=f"(o[0]), "=f"(o[1]) : "l"(acc1[j8 * 2]));
            asm("mov.b64 {%0,%1}, %2;" : "=f"(o[2]), "=f"(o[3]) : "l"(acc1[j8 * 2 + 1]));
            if (jb < 32)
                *(uint2*)(g_t2h + (size_t)n1 * 32 + jb) = pack_h4(o[0], o[1], o[2], o[3]);
            else
                *(float4*)(g_u2 + (size_t)n1 * 32 + (jb - 32)) = *(float4*)o;
        }
    }
}

// ---------------- gather-mean + epilogue kernels (fp16 gathers) ----------------
__global__ __launch_bounds__(256)
void aggH_kernel(const float* __restrict__ b1) {
    int tid = threadIdx.x;
    int g = tid >> 4;
    int c = tid & 15;
    int n = blockIdx.x * 16 + g;
    if (n >= N_NODES) return;
    int start = g_start[n], deg = g_deg[n], end = start + deg;
    float4 acc = make_float4(0.f, 0.f, 0.f, 0.f);
    int i = start;
    for (; i + 3 < end; i += 4) {
        int s0 = g_col[i], s1 = g_col[i + 1], s2 = g_col[i + 2], s3 = g_col[i + 3];
        float4 v0 = unpack_h4(*(const uint2*)(g_t1h + (size_t)s0 * 64 + c * 4));
        float4 v1 = unpack_h4(*(const uint2*)(g_t1h + (size_t)s1 * 64 + c * 4));
        float4 v2 = unpack_h4(*(const uint2*)(g_t1h + (size_t)s2 * 64 + c * 4));
        float4 v3 = unpack_h4(*(const uint2*)(g_t1h + (size_t)s3 * 64 + c * 4));
        acc.x += (v0.x + v1.x) + (v2.x + v3.x);
        acc.y += (v0.y + v1.y) + (v2.y + v3.y);
        acc.z += (v0.z + v1.z) + (v2.z + v3.z);
        acc.w += (v0.w + v1.w) + (v2.w + v3.w);
    }
    for (; i < end; i++) {
        int s0 = g_col[i];
        float4 v0 = unpack_h4(*(const uint2*)(g_t1h + (size_t)s0 * 64 + c * 4));
        acc.x += v0.x; acc.y += v0.y; acc.z += v0.z; acc.w += v0.w;
    }
    float inv = 1.0f / fmaxf((float)deg, 1.0f);
    float4 u = *(const float4*)(g_u1 + (size_t)n * 64 + c * 4);
    float4 bb = *(const float4*)(b1 + c * 4);
    float4 o;
    o.x = fmaxf(fmaf(acc.x, inv, u.x + bb.x), 0.0f);
    o.y = fmaxf(fmaf(acc.y, inv, u.y + bb.y), 0.0f);
    o.z = fmaxf(fmaf(acc.z, inv, u.z + bb.z), 0.0f);
    o.w = fmaxf(fmaf(acc.w, inv, u.w + bb.w), 0.0f);
    *(float4*)(g_h + (size_t)n * 64 + c * 4) = o;
}

__global__ __launch_bounds__(256)
void agg_final_kernel(const float* __restrict__ b2, float* __restrict__ out) {
    int tid = threadIdx.x;
    int g = tid >> 3;
    int c = tid & 7;
    int n = blockIdx.x * 32 + g;
    if (n >= N_NODES) return;
    int start = g_start[n], deg = g_deg[n], end = start + deg;
    float4 acc = make_float4(0.f, 0.f, 0.f, 0.f);
    int i = start;
    for (; i + 3 < end; i += 4) {
        int s0 = g_col[i], s1 = g_col[i + 1], s2 = g_col[i + 2], s3 = g_col[i + 3];
        float4 v0 = unpack_h4(*(const uint2*)(g_t2h + (size_t)s0 * 32 + c * 4));
        float4 v1 = unpack_h4(*(const uint2*)(g_t2h + (size_t)s1 * 32 + c * 4));
        float4 v2 = unpack_h4(*(const uint2*)(g_t2h + (size_t)s2 * 32 + c * 4));
        float4 v3 = unpack_h4(*(const uint2*)(g_t2h + (size_t)s3 * 32 + c * 4));
        acc.x += (v0.x + v1.x) + (v2.x + v3.x);
        acc.y += (v0.y + v1.y) + (v2.y + v3.y);
        acc.z += (v0.z + v1.z) + (v2.z + v3.z);
        acc.w += (v0.w + v1.w) + (v2.w + v3.w);
    }
    for (; i < end; i++) {
        int s0 = g_col[i];
        float4 v0 = unpack_h4(*(const uint2*)(g_t2h + (size_t)s0 * 32 + c * 4));
        acc.x += v0.x; acc.y += v0.y; acc.z += v0.z; acc.w += v0.w;
    }
    float inv = 1.0f / fmaxf((float)deg, 1.0f);
    float4 u = *(const float4*)(g_u2 + (size_t)n * 32 + c * 4);
    float4 bb = *(const float4*)(b2 + c * 4);
    float4 o;
    o.x = fmaf(acc.x, inv, u.x + bb.x);
    o.y = fmaf(acc.y, inv, u.y + bb.y);
    o.z = fmaf(acc.z, inv, u.z + bb.z);
    o.w = fmaf(acc.w, inv, u.w + bb.w);
    *(float4*)(out + (size_t)n * 32 + c * 4) = o;
}

// ---------------- launch ----------------
extern "C" void kernel_launch(void* const* d_in, const int* in_sizes, int n_in,
                              void* d_out, int out_size) {
    const float* x   = (const float*)d_in[0];
    const void*  ei  = d_in[1];
    const float* W1n = (const float*)d_in[2];
    const float* W1s = (const float*)d_in[3];
    const float* b1  = (const float*)d_in[4];
    const float* W2n = (const float*)d_in[5];
    const float* W2s = (const float*)d_in[6];
    const float* b2  = (const float*)d_in[7];
    float* out = (float*)d_out;
    int E = in_sizes[1] / 2;

    cudaStream_t s2;
    cudaStreamCreate(&s2);
    cudaEvent_t evFork, evJoin;
    cudaEventCreateWithFlags(&evFork, cudaEventDisableTiming);
    cudaEventCreateWithFlags(&evJoin, cudaEventDisableTiming);

    cudaEventRecord(evFork, 0);
    cudaStreamWaitEvent(s2, evFork, 0);

    // CSR build on side stream
    count_kernel<<<(E / 2 + 256) / 256, 256, 0, s2>>>(ei, E);
    offs_kernel<<<(N_NODES + 255) / 256, 256, 0, s2>>>();
    fill_kernel<<<(E / 2 + 256) / 256, 256, 0, s2>>>(ei, E);
    cudaEventRecord(evJoin, s2);

    // layer-1 GEMM on main stream, concurrent with CSR build
    gemmA_kernel<<<(N_NODES + 127) / 128, 256>>>(x, W1n, W1s);

    cudaStreamWaitEvent(0, evJoin, 0);

    aggH_kernel<<<(N_NODES + 15) / 16, 256>>>(b1);
    gemmD_kernel<<<(N_NODES + 127) / 128, 256>>>(W2n, W2s);
    agg_final_kernel<<<(N_NODES + 31) / 32, 256>>>(b2, out);

    cudaEventDestroy(evFork);
    cudaEventDestroy(evJoin);
    cudaStreamDestroy(s2);
}

// round 14
// speedup vs baseline: 1.5322x; 1.1440x over previous
#include <cuda_runtime.h>
#include <cuda_bf16.h>
#include <cuda_fp16.h>
#include <cstdint>

#define N_NODES 100000
#define N_EDGES 1600000

// ---------------- scratch (device globals; no allocations) ----------------
__device__ int    g_cnt[N_NODES];                 // degree histogram
__device__ int    g_total;                        // running segment allocator
__device__ int    g_rank[N_EDGES];                // per-edge rank within its dst
__device__ int    g_start[N_NODES];               // segment start per node
__device__ int    g_deg[N_NODES];                 // degree per node
__device__ int    g_col[N_EDGES];                 // CSR column (src) indices
__device__ __half g_t1h[(size_t)N_NODES * 64];    // x @ W1n   (fp16, gathered)
__device__ float  g_u1[(size_t)N_NODES * 64];     // x @ W1s   (fp32, sequential)
__device__ float  g_h [(size_t)N_NODES * 64];     // layer-1 output (relu)
__device__ __half g_t2h[(size_t)N_NODES * 32];    // h @ W2n   (fp16, gathered)
__device__ float  g_u2[(size_t)N_NODES * 32];     // h @ W2s   (fp32, sequential)

__device__ __forceinline__ int detect_is64(const int* ei32) {
    return (ei32[1] == 0 && ei32[3] == 0 && ei32[5] == 0 && ei32[7] == 0) ? 1 : 0;
}

__device__ __forceinline__ uint2 pack_h4(float a, float b, float c, float d) {
    __half2 lo = __floats2half2_rn(a, b);
    __half2 hi = __floats2half2_rn(c, d);
    uint2 r;
    r.x = *reinterpret_cast<unsigned*>(&lo);
    r.y = *reinterpret_cast<unsigned*>(&hi);
    return r;
}
__device__ __forceinline__ float4 unpack_h4(uint2 v) {
    float2 lo = __half22float2(*reinterpret_cast<__half2*>(&v.x));
    float2 hi = __half22float2(*reinterpret_cast<__half2*>(&v.y));
    return make_float4(lo.x, lo.y, hi.x, hi.y);
}
__device__ __forceinline__ unsigned f2tf32(float f) {
    unsigned r;
    asm("cvt.rna.tf32.f32 %0, %1;" : "=r"(r) : "f"(f));
    return r;
}

// ---------------- CSR build (3 kernels) ----------------
__global__ void count_kernel(const void* __restrict__ ei, int E) {
    int t = blockIdx.x * blockDim.x + threadIdx.x;
    if (t == 0) g_total = 0;
    int e0 = t * 2;
    if (e0 >= E) return;
    int is64 = detect_is64((const int*)ei);
    int d0, d1 = -1;
    if (is64) {
        const long long* p = (const long long*)ei + E;
        d0 = (int)p[e0];
        if (e0 + 1 < E) d1 = (int)p[e0 + 1];
    } else {
        const int* p = (const int*)ei + E;
        d0 = p[e0];
        if (e0 + 1 < E) d1 = p[e0 + 1];
    }
    int r0 = atomicAdd(&g_cnt[d0], 1);
    g_rank[e0] = r0;
    if (d1 >= 0) {
        int r1 = atomicAdd(&g_cnt[d1], 1);
        g_rank[e0 + 1] = r1;
    }
}

__global__ void offs_kernel() {
    int tid = threadIdx.x;
    int n = blockIdx.x * 256 + tid;
    int lane = tid & 31, wid = tid >> 5;
    int c = (n < N_NODES) ? g_cnt[n] : 0;

    int v = c;
    #pragma unroll
    for (int off = 1; off < 32; off <<= 1) {
        int t = __shfl_up_sync(0xffffffffu, v, off);
        if (lane >= off) v += t;
    }
    int excl = v - c;

    __shared__ int woff[8];
    __shared__ int bbase;
    if (lane == 31) woff[wid] = v;
    __syncthreads();
    if (wid == 0) {
        int orig = (lane < 8) ? woff[lane] : 0;
        int wv = orig;
        #pragma unroll
        for (int off = 1; off < 8; off <<= 1) {
            int t = __shfl_up_sync(0xffffffffu, wv, off);
            if (lane >= off) wv += t;
        }
        if (lane == 7) bbase = atomicAdd(&g_total, wv);
        if (lane < 8) woff[lane] = wv - orig;
    }
    __syncthreads();

    if (n < N_NODES) {
        g_start[n] = bbase + woff[wid] + excl;
        g_deg[n]   = c;
        g_cnt[n]   = 0;
    }
}

__global__ void fill_kernel(const void* __restrict__ ei, int E) {
    int t = blockIdx.x * blockDim.x + threadIdx.x;
    int e0 = t * 2;
    if (e0 >= E) return;
    int is64 = detect_is64((const int*)ei);
    int s0, d0, s1 = -1, d1 = -1;
    if (is64) {
        const long long* p = (const long long*)ei;
        s0 = (int)p[e0]; d0 = (int)p[E + e0];
        if (e0 + 1 < E) { s1 = (int)p[e0 + 1]; d1 = (int)p[E + e0 + 1]; }
    } else {
        const int* p = (const int*)ei;
        s0 = p[e0]; d0 = p[E + e0];
        if (e0 + 1 < E) { s1 = p[e0 + 1]; d1 = p[E + e0 + 1]; }
    }
    int p0 = g_start[d0] + g_rank[e0];
    g_col[p0] = s0;
    if (d1 >= 0) {
        int p1 = g_start[d1] + g_rank[e0 + 1];
        g_col[p1] = s1;
    }
}

// ---------------- layer-1 GEMM via tf32 tensor cores ----------------
// [t1|u1] = x @ [W1n|W1s]: M=128 nodes/block, N=128 outs, K=64 (2 chunks).
// 8 warps: warp_m = w&3 (32 rows), warp_n = w>>2 (64 cols).
// Fragments: mma.m16n8k8 tf32, A row-major from sX, B col-major from sW.
#define MMA_TF32(c, a, b0_, b1_) \
    asm volatile("mma.sync.aligned.m16n8k8.row.col.f32.tf32.tf32.f32 " \
        "{%0,%1,%2,%3}, {%4,%5,%6,%7}, {%8,%9}, {%0,%1,%2,%3};" \
        : "+f"((c)[0]), "+f"((c)[1]), "+f"((c)[2]), "+f"((c)[3]) \
        : "r"((a)[0]), "r"((a)[1]), "r"((a)[2]), "r"((a)[3]), \
          "r"(b0_), "r"(b1_))

__global__ __launch_bounds__(256, 2)
void gemmA_kernel(const float* __restrict__ src,
                  const float* __restrict__ Wa,   // [64, 64] = W1n
                  const float* __restrict__ Wb) { // [64, 64] = W1s
    constexpr int PX = 36;                // sX pitch (floats)
    constexpr int PW = 136;               // sW pitch (floats)
    __shared__ unsigned sX[128 * PX];     // 18.4KB (tf32 bits)
    __shared__ unsigned sW[32 * PW];      // 17.4KB

    int tid  = threadIdx.x;
    int base = blockIdx.x * 128;
    int w    = tid >> 5;
    int lane = tid & 31;
    int wm   = w & 3;                     // 0..3 -> rows wm*32..+32
    int wn   = w >> 2;                    // 0..1 -> cols wn*64..+64
    int gid  = lane >> 2;                 // 0..7
    int ctid = lane & 3;                  // 0..3

    // staging coords
    int k4 = tid & 7;
    int r_[4], nc_[4];
    #pragma unroll
    for (int it = 0; it < 4; it++) {
        r_[it] = (tid + it * 256) >> 3;            // 0..127
        int n = base + r_[it];
        nc_[it] = (n < N_NODES) ? n : (N_NODES - 1);
    }

    float acc[2][8][4];
    #pragma unroll
    for (int mt = 0; mt < 2; mt++)
        #pragma unroll
        for (int nt = 0; nt < 8; nt++)
            #pragma unroll
            for (int i = 0; i < 4; i++) acc[mt][nt][i] = 0.0f;

    #pragma unroll 1
    for (int c = 0; c < 2; c++) {
        if (c > 0) __syncthreads();       // previous chunk consumers done
        // stage X chunk: 128 rows x 32 k (tf32)
        #pragma unroll
        for (int it = 0; it < 4; it++) {
            float4 v = *(const float4*)(src + (size_t)nc_[it] * 64 + c * 32 + k4 * 4);
            unsigned* d = sX + r_[it] * PX + k4 * 4;
            d[0] = f2tf32(v.x); d[1] = f2tf32(v.y);
            d[2] = f2tf32(v.z); d[3] = f2tf32(v.w);
        }
        // stage W chunk: 32 k x 128 j (tf32)
        #pragma unroll
        for (int iw = 0; iw < 4; iw++) {
            int idx = tid + iw * 256;              // 0..1023 (float4 units)
            int kk = idx >> 5, jq = idx & 31;
            int k = c * 32 + kk;
            const float* wsrc = (jq < 16) ? (Wa + k * 64 + jq * 4)
                                          : (Wb + k * 64 + jq * 4 - 64);
            float4 v = *(const float4*)wsrc;
            unsigned* d = sW + kk * PW + jq * 4;
            d[0] = f2tf32(v.x); d[1] = f2tf32(v.y);
            d[2] = f2tf32(v.z); d[3] = f2tf32(v.w);
        }
        __syncthreads();

        #pragma unroll
        for (int ks = 0; ks < 4; ks++) {
            int k0 = ks * 8;
            unsigned a[2][4];
            #pragma unroll
            for (int mt = 0; mt < 2; mt++) {
                int row = wm * 32 + mt * 16 + gid;
                a[mt][0] = sX[row * PX + k0 + ctid];
                a[mt][1] = sX[(row + 8) * PX + k0 + ctid];
                a[mt][2] = sX[row * PX + k0 + ctid + 4];
                a[mt][3] = sX[(row + 8) * PX + k0 + ctid + 4];
            }
            #pragma unroll
            for (int nt = 0; nt < 8; nt++) {
                int j = wn * 64 + nt * 8 + gid;
                unsigned b0 = sW[(k0 + ctid) * PW + j];
                unsigned b1 = sW[(k0 + ctid + 4) * PW + j];
                MMA_TF32(acc[0][nt], a[0], b0, b1);
                MMA_TF32(acc[1][nt], a[1], b0, b1);
            }
        }
    }

    // epilogue: c0,c1 -> row gid, cols j,j+1; c2,c3 -> row gid+8
    #pragma unroll
    for (int mt = 0; mt < 2; mt++) {
        int n0 = base + wm * 32 + mt * 16 + gid;
        int n1 = n0 + 8;
        #pragma unroll
        for (int nt = 0; nt < 8; nt++) {
            int j = wn * 64 + nt * 8 + 2 * ctid;
            float* a = acc[mt][nt];
            if (n0 < N_NODES) {
                if (j < 64)
                    *(__half2*)(g_t1h + (size_t)n0 * 64 + j) = __floats2half2_rn(a[0], a[1]);
                else
                    *(float2*)(g_u1 + (size_t)n0 * 64 + (j - 64)) = make_float2(a[0], a[1]);
            }
            if (n1 < N_NODES) {
                if (j < 64)
                    *(__half2*)(g_t1h + (size_t)n1 * 64 + j) = __floats2half2_rn(a[2], a[3]);
                else
                    *(float2*)(g_u1 + (size_t)n1 * 64 + (j - 64)) = make_float2(a[2], a[3]);
            }
        }
    }
}

#define FMA2(acc, a2, b2) \
    asm("fma.rn.f32x2 %0, %1, %2, %0;" : "+l"(acc) : "l"(a2), "l"(b2))

// ---------------- layer-2 GEMM: t2(h16)=h@W2n, u2(f32)=h@W2s (scalar) ----------------
__global__ __launch_bounds__(256, 2)
void gemmD_kernel(const float* __restrict__ Wa,   // [64, 32] = W2n
                  const float* __restrict__ Wb) { // [64, 32] = W2s
    constexpr int OUT = 64, TPN = 4, NB = 128, HALF = 64, FP = 33;
    const float* src = g_h;
    __shared__ float sF[NB * FP];
    __shared__ float sW2[32 * OUT];

    int tid = threadIdx.x;
    int base = blockIdx.x * NB;
    int ln = tid / TPN;
    int q  = tid % TPN;
    int k4 = tid & 7;

    int r_[4], nc_[4];
    #pragma unroll
    for (int it = 0; it < 4; it++) {
        r_[it] = (tid + it * 256) >> 3;
        int n = base + r_[it];
        nc_[it] = (n < N_NODES) ? n : (N_NODES - 1);
    }
    float4 pf[4], pw[2];

    auto load_chunk = [&](int c) {
        #pragma unroll
        for (int it = 0; it < 4; it++)
            pf[it] = *(const float4*)(src + (size_t)nc_[it] * 64 + c * 32 + k4 * 4);
        #pragma unroll
        for (int iw = 0; iw < 2; iw++) {
            int idx = tid + iw * 256;
            int kk = idx >> 4, jq = idx & 15;
            int k = c * 32 + kk;
            const float* wsrc = (jq < 8) ? (Wa + k * 32 + jq * 4)
                                         : (Wb + k * 32 + jq * 4 - 32);
            pw[iw] = *(const float4*)wsrc;
        }
    };
    auto store_stage = [&]() {
        #pragma unroll
        for (int it = 0; it < 4; it++) {
            float* d = sF + r_[it] * FP + k4 * 4;
            d[0] = pf[it].x; d[1] = pf[it].y; d[2] = pf[it].z; d[3] = pf[it].w;
        }
        #pragma unroll
        for (int iw = 0; iw < 2; iw++)
            ((float4*)sW2)[tid + iw * 256] = pw[iw];
    };

    load_chunk(0);
    store_stage();
    __syncthreads();

    unsigned long long acc0[8] = {}, acc1[8] = {};
    const float* fp0 = sF + ln * FP;
    const float* fp1 = sF + (ln + HALF) * FP;
    const float* wq  = sW2 + (q << 2);

    #pragma unroll 1
    for (int c = 0; c < 2; c++) {
        if (c < 1) load_chunk(1);
        #pragma unroll 8
        for (int kk = 0; kk < 32; kk++) {
            float f0 = fp0[kk], f1 = fp1[kk];
            unsigned long long f0d, f1d;
            asm("mov.b64 %0, {%1,%1};" : "=l"(f0d) : "f"(f0));
            asm("mov.b64 %0, {%1,%1};" : "=l"(f1d) : "f"(f1));
            const float* wr = wq + kk * OUT;
            #pragma unroll
            for (int j8 = 0; j8 < 4; j8++) {
                ulonglong2 ww = *(const ulonglong2*)(wr + j8 * 16);
                FMA2(acc0[j8 * 2],     f0d, ww.x);
                FMA2(acc0[j8 * 2 + 1], f0d, ww.y);
                FMA2(acc1[j8 * 2],     f1d, ww.x);
                FMA2(acc1[j8 * 2 + 1], f1d, ww.y);
            }
        }
        __syncthreads();
        if (c < 1) { store_stage(); __syncthreads(); }
    }

    int n0 = base + ln, n1 = base + ln + HALF;
    #pragma unroll
    for (int j8 = 0; j8 < 4; j8++) {
        int jb = j8 * 16 + (q << 2);
        if (n0 < N_NODES) {
            float o[4];
            asm("mov.b64 {%0,%1}, %2;" : "=f"(o[0]), "=f"(o[1]) : "l"(acc0[j8 * 2]));
            asm("mov.b64 {%0,%1}, %2;" : "=f"(o[2]), "=f"(o[3]) : "l"(acc0[j8 * 2 + 1]));
            if (jb < 32)
                *(uint2*)(g_t2h + (size_t)n0 * 32 + jb) = pack_h4(o[0], o[1], o[2], o[3]);
            else
                *(float4*)(g_u2 + (size_t)n0 * 32 + (jb - 32)) = *(float4*)o;
        }
        if (n1 < N_NODES) {
            float o[4];
            asm("mov.b64 {%0,%1}, %2;" : "=f"(o[0]), "=f"(o[1]) : "l"(acc1[j8 * 2]));
            asm("mov.b64 {%0,%1}, %2;" : "=f"(o[2]), "=f"(o[3]) : "l"(acc1[j8 * 2 + 1]));
            if (jb < 32)
                *(uint2*)(g_t2h + (size_t)n1 * 32 + jb) = pack_h4(o[0], o[1], o[2], o[3]);
            else
                *(float4*)(g_u2 + (size_t)n1 * 32 + (jb - 32)) = *(float4*)o;
        }
    }
}

// ---------------- gather-mean + epilogue kernels (fp16 gathers) ----------------
__global__ __launch_bounds__(256)
void aggH_kernel(const float* __restrict__ b1) {
    int tid = threadIdx.x;
    int g = tid >> 4;
    int c = tid & 15;
    int n = blockIdx.x * 16 + g;
    if (n >= N_NODES) return;
    int start = g_start[n], deg = g_deg[n], end = start + deg;
    float4 acc = make_float4(0.f, 0.f, 0.f, 0.f);
    int i = start;
    for (; i + 3 < end; i += 4) {
        int s0 = g_col[i], s1 = g_col[i + 1], s2 = g_col[i + 2], s3 = g_col[i + 3];
        float4 v0 = unpack_h4(*(const uint2*)(g_t1h + (size_t)s0 * 64 + c * 4));
        float4 v1 = unpack_h4(*(const uint2*)(g_t1h + (size_t)s1 * 64 + c * 4));
        float4 v2 = unpack_h4(*(const uint2*)(g_t1h + (size_t)s2 * 64 + c * 4));
        float4 v3 = unpack_h4(*(const uint2*)(g_t1h + (size_t)s3 * 64 + c * 4));
        acc.x += (v0.x + v1.x) + (v2.x + v3.x);
        acc.y += (v0.y + v1.y) + (v2.y + v3.y);
        acc.z += (v0.z + v1.z) + (v2.z + v3.z);
        acc.w += (v0.w + v1.w) + (v2.w + v3.w);
    }
    for (; i < end; i++) {
        int s0 = g_col[i];
        float4 v0 = unpack_h4(*(const uint2*)(g_t1h + (size_t)s0 * 64 + c * 4));
        acc.x += v0.x; acc.y += v0.y; acc.z += v0.z; acc.w += v0.w;
    }
    float inv = 1.0f / fmaxf((float)deg, 1.0f);
    float4 u = *(const float4*)(g_u1 + (size_t)n * 64 + c * 4);
    float4 bb = *(const float4*)(b1 + c * 4);
    float4 o;
    o.x = fmaxf(fmaf(acc.x, inv, u.x + bb.x), 0.0f);
    o.y = fmaxf(fmaf(acc.y, inv, u.y + bb.y), 0.0f);
    o.z = fmaxf(fmaf(acc.z, inv, u.z + bb.z), 0.0f);
    o.w = fmaxf(fmaf(acc.w, inv, u.w + bb.w), 0.0f);
    *(float4*)(g_h + (size_t)n * 64 + c * 4) = o;
}

__global__ __launch_bounds__(256)
void agg_final_kernel(const float* __restrict__ b2, float* __restrict__ out) {
    int tid = threadIdx.x;
    int g = tid >> 3;
    int c = tid & 7;
    int n = blockIdx.x * 32 + g;
    if (n >= N_NODES) return;
    int start = g_start[n], deg = g_deg[n], end = start + deg;
    float4 acc = make_float4(0.f, 0.f, 0.f, 0.f);
    int i = start;
    for (; i + 3 < end; i += 4) {
        int s0 = g_col[i], s1 = g_col[i + 1], s2 = g_col[i + 2], s3 = g_col[i + 3];
        float4 v0 = unpack_h4(*(const uint2*)(g_t2h + (size_t)s0 * 32 + c * 4));
        float4 v1 = unpack_h4(*(const uint2*)(g_t2h + (size_t)s1 * 32 + c * 4));
        float4 v2 = unpack_h4(*(const uint2*)(g_t2h + (size_t)s2 * 32 + c * 4));
        float4 v3 = unpack_h4(*(const uint2*)(g_t2h + (size_t)s3 * 32 + c * 4));
        acc.x += (v0.x + v1.x) + (v2.x + v3.x);
        acc.y += (v0.y + v1.y) + (v2.y + v3.y);
        acc.z += (v0.z + v1.z) + (v2.z + v3.z);
        acc.w += (v0.w + v1.w) + (v2.w + v3.w);
    }
    for (; i < end; i++) {
        int s0 = g_col[i];
        float4 v0 = unpack_h4(*(const uint2*)(g_t2h + (size_t)s0 * 32 + c * 4));
        acc.x += v0.x; acc.y += v0.y; acc.z += v0.z; acc.w += v0.w;
    }
    float inv = 1.0f / fmaxf((float)deg, 1.0f);
    float4 u = *(const float4*)(g_u2 + (size_t)n * 32 + c * 4);
    float4 bb = *(const float4*)(b2 + c * 4);
    float4 o;
    o.x = fmaf(acc.x, inv, u.x + bb.x);
    o.y = fmaf(acc.y, inv, u.y + bb.y);
    o.z = fmaf(acc.z, inv, u.z + bb.z);
    o.w = fmaf(acc.w, inv, u.w + bb.w);
    *(float4*)(out + (size_t)n * 32 + c * 4) = o;
}

// ---------------- launch ----------------
extern "C" void kernel_launch(void* const* d_in, const int* in_sizes, int n_in,
                              void* d_out, int out_size) {
    const float* x   = (const float*)d_in[0];
    const void*  ei  = d_in[1];
    const float* W1n = (const float*)d_in[2];
    const float* W1s = (const float*)d_in[3];
    const float* b1  = (const float*)d_in[4];
    const float* W2n = (const float*)d_in[5];
    const float* W2s = (const float*)d_in[6];
    const float* b2  = (const float*)d_in[7];
    float* out = (float*)d_out;
    int E = in_sizes[1] / 2;

    cudaStream_t s2;
    cudaStreamCreate(&s2);
    cudaEvent_t evFork, evJoin;
    cudaEventCreateWithFlags(&evFork, cudaEventDisableTiming);
    cudaEventCreateWithFlags(&evJoin, cudaEventDisableTiming);

    cudaEventRecord(evFork, 0);
    cudaStreamWaitEvent(s2, evFork, 0);

    // CSR build on side stream
    count_kernel<<<(E / 2 + 256) / 256, 256, 0, s2>>>(ei, E);
    offs_kernel<<<(N_NODES + 255) / 256, 256, 0, s2>>>();
    fill_kernel<<<(E / 2 + 256) / 256, 256, 0, s2>>>(ei, E);
    cudaEventRecord(evJoin, s2);

    // layer-1 GEMM (tensor cores) on main stream, concurrent with CSR build
    gemmA_kernel<<<(N_NODES + 127) / 128, 256>>>(x, W1n, W1s);

    cudaStreamWaitEvent(0, evJoin, 0);

    aggH_kernel<<<(N_NODES + 15) / 16, 256>>>(b1);
    gemmD_kernel<<<(N_NODES + 127) / 128, 256>>>(W2n, W2s);
    agg_final_kernel<<<(N_NODES + 31) / 32, 256>>>(b2, out);

    cudaEventDestroy(evFork);
    cudaEventDestroy(evJoin);
    cudaStreamDestroy(s2);
}

// round 15
// speedup vs baseline: 1.7856x; 1.1654x over previous
#include <cuda_runtime.h>
#include <cuda_bf16.h>
#include <cuda_fp16.h>
#include <cstdint>

#define N_NODES 100000
#define N_EDGES 1600000

// ---------------- scratch (device globals; no allocations) ----------------
__device__ int    g_cnt[N_NODES];                 // degree histogram
__device__ int    g_total;                        // running segment allocator
__device__ int    g_rank[N_EDGES];                // per-edge rank within its dst
__device__ int    g_start[N_NODES];               // segment start per node
__device__ int    g_deg[N_NODES];                 // degree per node
__device__ int    g_col[N_EDGES];                 // CSR column (src) indices
__device__ __half g_t1h[(size_t)N_NODES * 64];    // x @ W1n   (fp16, gathered)
__device__ float  g_u1[(size_t)N_NODES * 64];     // x @ W1s   (fp32, sequential)
__device__ float  g_h [(size_t)N_NODES * 64];     // layer-1 output (relu)
__device__ __half g_t2h[(size_t)N_NODES * 32];    // h @ W2n   (fp16, gathered)
__device__ float  g_u2[(size_t)N_NODES * 32];     // h @ W2s   (fp32, sequential)

__device__ __forceinline__ int detect_is64(const int* ei32) {
    return (ei32[1] == 0 && ei32[3] == 0 && ei32[5] == 0 && ei32[7] == 0) ? 1 : 0;
}

__device__ __forceinline__ float4 unpack_h4(uint2 v) {
    float2 lo = __half22float2(*reinterpret_cast<__half2*>(&v.x));
    float2 hi = __half22float2(*reinterpret_cast<__half2*>(&v.y));
    return make_float4(lo.x, lo.y, hi.x, hi.y);
}
__device__ __forceinline__ unsigned f2tf32(float f) {
    unsigned r;
    asm("cvt.rna.tf32.f32 %0, %1;" : "=r"(r) : "f"(f));
    return r;
}

// ---------------- CSR build (3 kernels) ----------------
__global__ void count_kernel(const void* __restrict__ ei, int E) {
    int t = blockIdx.x * blockDim.x + threadIdx.x;
    if (t == 0) g_total = 0;
    int e0 = t * 2;
    if (e0 >= E) return;
    int is64 = detect_is64((const int*)ei);
    int d0, d1 = -1;
    if (is64) {
        const long long* p = (const long long*)ei + E;
        d0 = (int)p[e0];
        if (e0 + 1 < E) d1 = (int)p[e0 + 1];
    } else {
        const int* p = (const int*)ei + E;
        d0 = p[e0];
        if (e0 + 1 < E) d1 = p[e0 + 1];
    }
    int r0 = atomicAdd(&g_cnt[d0], 1);
    g_rank[e0] = r0;
    if (d1 >= 0) {
        int r1 = atomicAdd(&g_cnt[d1], 1);
        g_rank[e0 + 1] = r1;
    }
}

__global__ void offs_kernel() {
    int tid = threadIdx.x;
    int n = blockIdx.x * 256 + tid;
    int lane = tid & 31, wid = tid >> 5;
    int c = (n < N_NODES) ? g_cnt[n] : 0;

    int v = c;
    #pragma unroll
    for (int off = 1; off < 32; off <<= 1) {
        int t = __shfl_up_sync(0xffffffffu, v, off);
        if (lane >= off) v += t;
    }
    int excl = v - c;

    __shared__ int woff[8];
    __shared__ int bbase;
    if (lane == 31) woff[wid] = v;
    __syncthreads();
    if (wid == 0) {
        int orig = (lane < 8) ? woff[lane] : 0;
        int wv = orig;
        #pragma unroll
        for (int off = 1; off < 8; off <<= 1) {
            int t = __shfl_up_sync(0xffffffffu, wv, off);
            if (lane >= off) wv += t;
        }
        if (lane == 7) bbase = atomicAdd(&g_total, wv);
        if (lane < 8) woff[lane] = wv - orig;
    }
    __syncthreads();

    if (n < N_NODES) {
        g_start[n] = bbase + woff[wid] + excl;
        g_deg[n]   = c;
        g_cnt[n]   = 0;
    }
}

__global__ void fill_kernel(const void* __restrict__ ei, int E) {
    int t = blockIdx.x * blockDim.x + threadIdx.x;
    int e0 = t * 2;
    if (e0 >= E) return;
    int is64 = detect_is64((const int*)ei);
    int s0, d0, s1 = -1, d1 = -1;
    if (is64) {
        const long long* p = (const long long*)ei;
        s0 = (int)p[e0]; d0 = (int)p[E + e0];
        if (e0 + 1 < E) { s1 = (int)p[e0 + 1]; d1 = (int)p[E + e0 + 1]; }
    } else {
        const int* p = (const int*)ei;
        s0 = p[e0]; d0 = p[E + e0];
        if (e0 + 1 < E) { s1 = p[e0 + 1]; d1 = p[E + e0 + 1]; }
    }
    int p0 = g_start[d0] + g_rank[e0];
    g_col[p0] = s0;
    if (d1 >= 0) {
        int p1 = g_start[d1] + g_rank[e0 + 1];
        g_col[p1] = s1;
    }
}

// ---------------- tf32 tensor-core MMA macro ----------------
#define MMA_TF32(c, a, b0_, b1_) \
    asm volatile("mma.sync.aligned.m16n8k8.row.col.f32.tf32.tf32.f32 " \
        "{%0,%1,%2,%3}, {%4,%5,%6,%7}, {%8,%9}, {%0,%1,%2,%3};" \
        : "+f"((c)[0]), "+f"((c)[1]), "+f"((c)[2]), "+f"((c)[3]) \
        : "r"((a)[0]), "r"((a)[1]), "r"((a)[2]), "r"((a)[3]), \
          "r"(b0_), "r"(b1_))

// ---------------- layer-1 GEMM via tf32 tensor cores ----------------
// [t1|u1] = x @ [W1n|W1s]: M=128 nodes/block, N=128 outs, K=64 (2 chunks).
__global__ __launch_bounds__(256, 2)
void gemmA_kernel(const float* __restrict__ src,
                  const float* __restrict__ Wa,   // [64, 64] = W1n
                  const float* __restrict__ Wb) { // [64, 64] = W1s
    constexpr int PX = 36;
    constexpr int PW = 136;
    __shared__ unsigned sX[128 * PX];
    __shared__ unsigned sW[32 * PW];

    int tid  = threadIdx.x;
    int base = blockIdx.x * 128;
    int w    = tid >> 5;
    int lane = tid & 31;
    int wm   = w & 3;
    int wn   = w >> 2;
    int gid  = lane >> 2;
    int ctid = lane & 3;

    int k4 = tid & 7;
    int r_[4], nc_[4];
    #pragma unroll
    for (int it = 0; it < 4; it++) {
        r_[it] = (tid + it * 256) >> 3;
        int n = base + r_[it];
        nc_[it] = (n < N_NODES) ? n : (N_NODES - 1);
    }

    float acc[2][8][4];
    #pragma unroll
    for (int mt = 0; mt < 2; mt++)
        #pragma unroll
        for (int nt = 0; nt < 8; nt++)
            #pragma unroll
            for (int i = 0; i < 4; i++) acc[mt][nt][i] = 0.0f;

    #pragma unroll 1
    for (int c = 0; c < 2; c++) {
        if (c > 0) __syncthreads();
        #pragma unroll
        for (int it = 0; it < 4; it++) {
            float4 v = *(const float4*)(src + (size_t)nc_[it] * 64 + c * 32 + k4 * 4);
            unsigned* d = sX + r_[it] * PX + k4 * 4;
            d[0] = f2tf32(v.x); d[1] = f2tf32(v.y);
            d[2] = f2tf32(v.z); d[3] = f2tf32(v.w);
        }
        #pragma unroll
        for (int iw = 0; iw < 4; iw++) {
            int idx = tid + iw * 256;
            int kk = idx >> 5, jq = idx & 31;
            int k = c * 32 + kk;
            const float* wsrc = (jq < 16) ? (Wa + k * 64 + jq * 4)
                                          : (Wb + k * 64 + jq * 4 - 64);
            float4 v = *(const float4*)wsrc;
            unsigned* d = sW + kk * PW + jq * 4;
            d[0] = f2tf32(v.x); d[1] = f2tf32(v.y);
            d[2] = f2tf32(v.z); d[3] = f2tf32(v.w);
        }
        __syncthreads();

        #pragma unroll
        for (int ks = 0; ks < 4; ks++) {
            int k0 = ks * 8;
            unsigned a[2][4];
            #pragma unroll
            for (int mt = 0; mt < 2; mt++) {
                int row = wm * 32 + mt * 16 + gid;
                a[mt][0] = sX[row * PX + k0 + ctid];
                a[mt][1] = sX[(row + 8) * PX + k0 + ctid];
                a[mt][2] = sX[row * PX + k0 + ctid + 4];
                a[mt][3] = sX[(row + 8) * PX + k0 + ctid + 4];
            }
            #pragma unroll
            for (int nt = 0; nt < 8; nt++) {
                int j = wn * 64 + nt * 8 + gid;
                unsigned b0 = sW[(k0 + ctid) * PW + j];
                unsigned b1 = sW[(k0 + ctid + 4) * PW + j];
                MMA_TF32(acc[0][nt], a[0], b0, b1);
                MMA_TF32(acc[1][nt], a[1], b0, b1);
            }
        }
    }

    #pragma unroll
    for (int mt = 0; mt < 2; mt++) {
        int n0 = base + wm * 32 + mt * 16 + gid;
        int n1 = n0 + 8;
        #pragma unroll
        for (int nt = 0; nt < 8; nt++) {
            int j = wn * 64 + nt * 8 + 2 * ctid;
            float* a = acc[mt][nt];
            if (n0 < N_NODES) {
                if (j < 64)
                    *(__half2*)(g_t1h + (size_t)n0 * 64 + j) = __floats2half2_rn(a[0], a[1]);
                else
                    *(float2*)(g_u1 + (size_t)n0 * 64 + (j - 64)) = make_float2(a[0], a[1]);
            }
            if (n1 < N_NODES) {
                if (j < 64)
                    *(__half2*)(g_t1h + (size_t)n1 * 64 + j) = __floats2half2_rn(a[2], a[3]);
                else
                    *(float2*)(g_u1 + (size_t)n1 * 64 + (j - 64)) = make_float2(a[2], a[3]);
            }
        }
    }
}

// ---------------- layer-2 GEMM via tf32 tensor cores ----------------
// [t2|u2] = h @ [W2n|W2s]: M=128 nodes/block, N=64 outs, K=64 (2 chunks).
// 8 warps: wm = w&3 (32 rows), wn = w>>2 (32 cols each).
__global__ __launch_bounds__(256, 2)
void gemmD_kernel(const float* __restrict__ Wa,   // [64, 32] = W2n
                  const float* __restrict__ Wb) { // [64, 32] = W2s
    constexpr int PX = 36;
    constexpr int PW = 72;
    const float* src = g_h;
    __shared__ unsigned sX[128 * PX];   // 18.4KB
    __shared__ unsigned sW[32 * PW];    // 9.2KB

    int tid  = threadIdx.x;
    int base = blockIdx.x * 128;
    int w    = tid >> 5;
    int lane = tid & 31;
    int wm   = w & 3;
    int wn   = w >> 2;
    int gid  = lane >> 2;
    int ctid = lane & 3;

    int k4 = tid & 7;
    int r_[4], nc_[4];
    #pragma unroll
    for (int it = 0; it < 4; it++) {
        r_[it] = (tid + it * 256) >> 3;
        int n = base + r_[it];
        nc_[it] = (n < N_NODES) ? n : (N_NODES - 1);
    }

    float acc[2][4][4];
    #pragma unroll
    for (int mt = 0; mt < 2; mt++)
        #pragma unroll
        for (int nt = 0; nt < 4; nt++)
            #pragma unroll
            for (int i = 0; i < 4; i++) acc[mt][nt][i] = 0.0f;

    #pragma unroll 1
    for (int c = 0; c < 2; c++) {
        if (c > 0) __syncthreads();
        // stage h chunk: 128 rows x 32 k
        #pragma unroll
        for (int it = 0; it < 4; it++) {
            float4 v = *(const float4*)(src + (size_t)nc_[it] * 64 + c * 32 + k4 * 4);
            unsigned* d = sX + r_[it] * PX + k4 * 4;
            d[0] = f2tf32(v.x); d[1] = f2tf32(v.y);
            d[2] = f2tf32(v.z); d[3] = f2tf32(v.w);
        }
        // stage W chunk: 32 k x 64 j (j<32 = W2n, j>=32 = W2s)
        #pragma unroll
        for (int iw = 0; iw < 2; iw++) {
            int idx = tid + iw * 256;           // 0..511 (float4 units)
            int kk = idx >> 4, jq = idx & 15;
            int k = c * 32 + kk;
            const float* wsrc = (jq < 8) ? (Wa + k * 32 + jq * 4)
                                         : (Wb + k * 32 + (jq - 8) * 4);
            float4 v = *(const float4*)wsrc;
            unsigned* d = sW + kk * PW + jq * 4;
            d[0] = f2tf32(v.x); d[1] = f2tf32(v.y);
            d[2] = f2tf32(v.z); d[3] = f2tf32(v.w);
        }
        __syncthreads();

        #pragma unroll
        for (int ks = 0; ks < 4; ks++) {
            int k0 = ks * 8;
            unsigned a[2][4];
            #pragma unroll
            for (int mt = 0; mt < 2; mt++) {
                int row = wm * 32 + mt * 16 + gid;
                a[mt][0] = sX[row * PX + k0 + ctid];
                a[mt][1] = sX[(row + 8) * PX + k0 + ctid];
                a[mt][2] = sX[row * PX + k0 + ctid + 4];
                a[mt][3] = sX[(row + 8) * PX + k0 + ctid + 4];
            }
            #pragma unroll
            for (int nt = 0; nt < 4; nt++) {
                int j = wn * 32 + nt * 8 + gid;
                unsigned b0 = sW[(k0 + ctid) * PW + j];
                unsigned b1 = sW[(k0 + ctid + 4) * PW + j];
                MMA_TF32(acc[0][nt], a[0], b0, b1);
                MMA_TF32(acc[1][nt], a[1], b0, b1);
            }
        }
    }

    #pragma unroll
    for (int mt = 0; mt < 2; mt++) {
        int n0 = base + wm * 32 + mt * 16 + gid;
        int n1 = n0 + 8;
        #pragma unroll
        for (int nt = 0; nt < 4; nt++) {
            int j = wn * 32 + nt * 8 + 2 * ctid;
            float* a = acc[mt][nt];
            if (n0 < N_NODES) {
                if (j < 32)
                    *(__half2*)(g_t2h + (size_t)n0 * 32 + j) = __floats2half2_rn(a[0], a[1]);
                else
                    *(float2*)(g_u2 + (size_t)n0 * 32 + (j - 32)) = make_float2(a[0], a[1]);
            }
            if (n1 < N_NODES) {
                if (j < 32)
                    *(__half2*)(g_t2h + (size_t)n1 * 32 + j) = __floats2half2_rn(a[2], a[3]);
                else
                    *(float2*)(g_u2 + (size_t)n1 * 32 + (j - 32)) = make_float2(a[2], a[3]);
            }
        }
    }
}

// ---------------- gather-mean + epilogue kernels (fp16 gathers) ----------------
__global__ __launch_bounds__(256)
void aggH_kernel(const float* __restrict__ b1) {
    int tid = threadIdx.x;
    int g = tid >> 4;
    int c = tid & 15;
    int n = blockIdx.x * 16 + g;
    if (n >= N_NODES) return;
    int start = g_start[n], deg = g_deg[n], end = start + deg;
    float4 acc = make_float4(0.f, 0.f, 0.f, 0.f);
    int i = start;
    for (; i + 3 < end; i += 4) {
        int s0 = g_col[i], s1 = g_col[i + 1], s2 = g_col[i + 2], s3 = g_col[i + 3];
        float4 v0 = unpack_h4(*(const uint2*)(g_t1h + (size_t)s0 * 64 + c * 4));
        float4 v1 = unpack_h4(*(const uint2*)(g_t1h + (size_t)s1 * 64 + c * 4));
        float4 v2 = unpack_h4(*(const uint2*)(g_t1h + (size_t)s2 * 64 + c * 4));
        float4 v3 = unpack_h4(*(const uint2*)(g_t1h + (size_t)s3 * 64 + c * 4));
        acc.x += (v0.x + v1.x) + (v2.x + v3.x);
        acc.y += (v0.y + v1.y) + (v2.y + v3.y);
        acc.z += (v0.z + v1.z) + (v2.z + v3.z);
        acc.w += (v0.w + v1.w) + (v2.w + v3.w);
    }
    for (; i < end; i++) {
        int s0 = g_col[i];
        float4 v0 = unpack_h4(*(const uint2*)(g_t1h + (size_t)s0 * 64 + c * 4));
        acc.x += v0.x; acc.y += v0.y; acc.z += v0.z; acc.w += v0.w;
    }
    float inv = 1.0f / fmaxf((float)deg, 1.0f);
    float4 u = *(const float4*)(g_u1 + (size_t)n * 64 + c * 4);
    float4 bb = *(const float4*)(b1 + c * 4);
    float4 o;
    o.x = fmaxf(fmaf(acc.x, inv, u.x + bb.x), 0.0f);
    o.y = fmaxf(fmaf(acc.y, inv, u.y + bb.y), 0.0f);
    o.z = fmaxf(fmaf(acc.z, inv, u.z + bb.z), 0.0f);
    o.w = fmaxf(fmaf(acc.w, inv, u.w + bb.w), 0.0f);
    *(float4*)(g_h + (size_t)n * 64 + c * 4) = o;
}

__global__ __launch_bounds__(256)
void agg_final_kernel(const float* __restrict__ b2, float* __restrict__ out) {
    int tid = threadIdx.x;
    int g = tid >> 3;
    int c = tid & 7;
    int n = blockIdx.x * 32 + g;
    if (n >= N_NODES) return;
    int start = g_start[n], deg = g_deg[n], end = start + deg;
    float4 acc = make_float4(0.f, 0.f, 0.f, 0.f);
    int i = start;
    for (; i + 3 < end; i += 4) {
        int s0 = g_col[i], s1 = g_col[i + 1], s2 = g_col[i + 2], s3 = g_col[i + 3];
        float4 v0 = unpack_h4(*(const uint2*)(g_t2h + (size_t)s0 * 32 + c * 4));
        float4 v1 = unpack_h4(*(const uint2*)(g_t2h + (size_t)s1 * 32 + c * 4));
        float4 v2 = unpack_h4(*(const uint2*)(g_t2h + (size_t)s2 * 32 + c * 4));
        float4 v3 = unpack_h4(*(const uint2*)(g_t2h + (size_t)s3 * 32 + c * 4));
        acc.x += (v0.x + v1.x) + (v2.x + v3.x);
        acc.y += (v0.y + v1.y) + (v2.y + v3.y);
        acc.z += (v0.z + v1.z) + (v2.z + v3.z);
        acc.w += (v0.w + v1.w) + (v2.w + v3.w);
    }
    for (; i < end; i++) {
        int s0 = g_col[i];
        float4 v0 = unpack_h4(*(const uint2*)(g_t2h + (size_t)s0 * 32 + c * 4));
        acc.x += v0.x; acc.y += v0.y; acc.z += v0.z; acc.w += v0.w;
    }
    float inv = 1.0f / fmaxf((float)deg, 1.0f);
    float4 u = *(const float4*)(g_u2 + (size_t)n * 32 + c * 4);
    float4 bb = *(const float4*)(b2 + c * 4);
    float4 o;
    o.x = fmaf(acc.x, inv, u.x + bb.x);
    o.y = fmaf(acc.y, inv, u.y + bb.y);
    o.z = fmaf(acc.z, inv, u.z + bb.z);
    o.w = fmaf(acc.w, inv, u.w + bb.w);
    *(float4*)(out + (size_t)n * 32 + c * 4) = o;
}

// ---------------- launch ----------------
extern "C" void kernel_launch(void* const* d_in, const int* in_sizes, int n_in,
                              void* d_out, int out_size) {
    const float* x   = (const float*)d_in[0];
    const void*  ei  = d_in[1];
    const float* W1n = (const float*)d_in[2];
    const float* W1s = (const float*)d_in[3];
    const float* b1  = (const float*)d_in[4];
    const float* W2n = (const float*)d_in[5];
    const float* W2s = (const float*)d_in[6];
    const float* b2  = (const float*)d_in[7];
    float* out = (float*)d_out;
    int E = in_sizes[1] / 2;

    cudaStream_t s2;
    cudaStreamCreate(&s2);
    cudaEvent_t evFork, evJoin;
    cudaEventCreateWithFlags(&evFork, cudaEventDisableTiming);
    cudaEventCreateWithFlags(&evJoin, cudaEventDisableTiming);

    cudaEventRecord(evFork, 0);
    cudaStreamWaitEvent(s2, evFork, 0);

    // CSR build on side stream
    count_kernel<<<(E / 2 + 256) / 256, 256, 0, s2>>>(ei, E);
    offs_kernel<<<(N_NODES + 255) / 256, 256, 0, s2>>>();
    fill_kernel<<<(E / 2 + 256) / 256, 256, 0, s2>>>(ei, E);
    cudaEventRecord(evJoin, s2);

    // layer-1 GEMM (tensor cores) on main stream, concurrent with CSR build
    gemmA_kernel<<<(N_NODES + 127) / 128, 256>>>(x, W1n, W1s);

    cudaStreamWaitEvent(0, evJoin, 0);

    aggH_kernel<<<(N_NODES + 15) / 16, 256>>>(b1);
    gemmD_kernel<<<(N_NODES + 127) / 128, 256>>>(W2n, W2s);
    agg_final_kernel<<<(N_NODES + 31) / 32, 256>>>(b2, out);

    cudaEventDestroy(evFork);
    cudaEventDestroy(evJoin);
    cudaStreamDestroy(s2);
}

// round 16
// speedup vs baseline: 1.9037x; 1.0661x over previous
#include <cuda_runtime.h>
#include <cuda_bf16.h>
#include <cuda_fp16.h>
#include <cstdint>

#define N_NODES 100000
#define N_EDGES 1600000

// ---------------- scratch (device globals; no allocations) ----------------
__device__ int    g_cnt[N_NODES];                 // degree histogram
__device__ int    g_total;                        // running segment allocator
__device__ int    g_rank[N_EDGES];                // per-edge rank within its dst
__device__ int    g_start[N_NODES];               // segment start per node
__device__ int    g_deg[N_NODES];                 // degree per node
__device__ int    g_col[N_EDGES];                 // CSR column (src) indices
__device__ __half g_t1h[(size_t)N_NODES * 64];    // x @ W1n   (fp16, gathered)
__device__ float  g_u1[(size_t)N_NODES * 64];     // x @ W1s   (fp32, sequential)
__device__ float  g_h [(size_t)N_NODES * 64];     // layer-1 output (relu)
__device__ __half g_t2h[(size_t)N_NODES * 32];    // h @ W2n   (fp16, gathered)
__device__ float  g_u2[(size_t)N_NODES * 32];     // h @ W2s   (fp32, sequential)

__device__ __forceinline__ int detect_is64(const int* ei32) {
    return (ei32[1] == 0 && ei32[3] == 0 && ei32[5] == 0 && ei32[7] == 0) ? 1 : 0;
}

__device__ __forceinline__ unsigned f2tf32(float f) {
    unsigned r;
    asm("cvt.rna.tf32.f32 %0, %1;" : "=r"(r) : "f"(f));
    return r;
}
// accumulate 8 halves (one uint4) into 8 float accumulators
__device__ __forceinline__ void acc_h8(float* acc, uint4 v) {
    float2 a = __half22float2(*reinterpret_cast<__half2*>(&v.x));
    float2 b = __half22float2(*reinterpret_cast<__half2*>(&v.y));
    float2 c = __half22float2(*reinterpret_cast<__half2*>(&v.z));
    float2 d = __half22float2(*reinterpret_cast<__half2*>(&v.w));
    acc[0] += a.x; acc[1] += a.y; acc[2] += b.x; acc[3] += b.y;
    acc[4] += c.x; acc[5] += c.y; acc[6] += d.x; acc[7] += d.y;
}

// ---------------- CSR build (3 kernels, 4 edges/thread) ----------------
__global__ void count_kernel(const void* __restrict__ ei, int E) {
    int t = blockIdx.x * blockDim.x + threadIdx.x;
    if (t == 0) g_total = 0;
    int e0 = t * 4;
    if (e0 >= E) return;
    int is64 = detect_is64((const int*)ei);
    int m = E - e0; if (m > 4) m = 4;
    int d[4];
    if (is64) {
        const long long* p = (const long long*)ei + E;
        #pragma unroll
        for (int i = 0; i < 4; i++) if (i < m) d[i] = (int)p[e0 + i];
    } else {
        const int* p = (const int*)ei + E;
        #pragma unroll
        for (int i = 0; i < 4; i++) if (i < m) d[i] = p[e0 + i];
    }
    int r[4];
    #pragma unroll
    for (int i = 0; i < 4; i++) if (i < m) r[i] = atomicAdd(&g_cnt[d[i]], 1);
    #pragma unroll
    for (int i = 0; i < 4; i++) if (i < m) g_rank[e0 + i] = r[i];
}

__global__ void offs_kernel() {
    int tid = threadIdx.x;
    int n = blockIdx.x * 256 + tid;
    int lane = tid & 31, wid = tid >> 5;
    int c = (n < N_NODES) ? g_cnt[n] : 0;

    int v = c;
    #pragma unroll
    for (int off = 1; off < 32; off <<= 1) {
        int t = __shfl_up_sync(0xffffffffu, v, off);
        if (lane >= off) v += t;
    }
    int excl = v - c;

    __shared__ int woff[8];
    __shared__ int bbase;
    if (lane == 31) woff[wid] = v;
    __syncthreads();
    if (wid == 0) {
        int orig = (lane < 8) ? woff[lane] : 0;
        int wv = orig;
        #pragma unroll
        for (int off = 1; off < 8; off <<= 1) {
            int t = __shfl_up_sync(0xffffffffu, wv, off);
            if (lane >= off) wv += t;
        }
        if (lane == 7) bbase = atomicAdd(&g_total, wv);
        if (lane < 8) woff[lane] = wv - orig;
    }
    __syncthreads();

    if (n < N_NODES) {
        g_start[n] = bbase + woff[wid] + excl;
        g_deg[n]   = c;
        g_cnt[n]   = 0;
    }
}

__global__ void fill_kernel(const void* __restrict__ ei, int E) {
    int t = blockIdx.x * blockDim.x + threadIdx.x;
    int e0 = t * 4;
    if (e0 >= E) return;
    int is64 = detect_is64((const int*)ei);
    int m = E - e0; if (m > 4) m = 4;
    int s[4], d[4];
    if (is64) {
        const long long* p = (const long long*)ei;
        #pragma unroll
        for (int i = 0; i < 4; i++) if (i < m) { s[i] = (int)p[e0 + i]; d[i] = (int)p[E + e0 + i]; }
    } else {
        const int* p = (const int*)ei;
        #pragma unroll
        for (int i = 0; i < 4; i++) if (i < m) { s[i] = p[e0 + i]; d[i] = p[E + e0 + i]; }
    }
    int rk[4], st[4];
    #pragma unroll
    for (int i = 0; i < 4; i++) if (i < m) rk[i] = g_rank[e0 + i];
    #pragma unroll
    for (int i = 0; i < 4; i++) if (i < m) st[i] = g_start[d[i]];
    #pragma unroll
    for (int i = 0; i < 4; i++) if (i < m) g_col[st[i] + rk[i]] = s[i];
}

// ---------------- tf32 tensor-core MMA macro ----------------
#define MMA_TF32(c, a, b0_, b1_) \
    asm volatile("mma.sync.aligned.m16n8k8.row.col.f32.tf32.tf32.f32 " \
        "{%0,%1,%2,%3}, {%4,%5,%6,%7}, {%8,%9}, {%0,%1,%2,%3};" \
        : "+f"((c)[0]), "+f"((c)[1]), "+f"((c)[2]), "+f"((c)[3]) \
        : "r"((a)[0]), "r"((a)[1]), "r"((a)[2]), "r"((a)[3]), \
          "r"(b0_), "r"(b1_))

// ---------------- layer-1 GEMM via tf32 tensor cores ----------------
__global__ __launch_bounds__(256, 2)
void gemmA_kernel(const float* __restrict__ src,
                  const float* __restrict__ Wa,   // [64, 64] = W1n
                  const float* __restrict__ Wb) { // [64, 64] = W1s
    constexpr int PX = 36;
    constexpr int PW = 136;
    __shared__ unsigned sX[128 * PX];
    __shared__ unsigned sW[32 * PW];

    int tid  = threadIdx.x;
    int base = blockIdx.x * 128;
    int w    = tid >> 5;
    int lane = tid & 31;
    int wm   = w & 3;
    int wn   = w >> 2;
    int gid  = lane >> 2;
    int ctid = lane & 3;

    int k4 = tid & 7;
    int r_[4], nc_[4];
    #pragma unroll
    for (int it = 0; it < 4; it++) {
        r_[it] = (tid + it * 256) >> 3;
        int n = base + r_[it];
        nc_[it] = (n < N_NODES) ? n : (N_NODES - 1);
    }

    float acc[2][8][4];
    #pragma unroll
    for (int mt = 0; mt < 2; mt++)
        #pragma unroll
        for (int nt = 0; nt < 8; nt++)
            #pragma unroll
            for (int i = 0; i < 4; i++) acc[mt][nt][i] = 0.0f;

    #pragma unroll 1
    for (int c = 0; c < 2; c++) {
        if (c > 0) __syncthreads();
        #pragma unroll
        for (int it = 0; it < 4; it++) {
            float4 v = *(const float4*)(src + (size_t)nc_[it] * 64 + c * 32 + k4 * 4);
            unsigned* d = sX + r_[it] * PX + k4 * 4;
            d[0] = f2tf32(v.x); d[1] = f2tf32(v.y);
            d[2] = f2tf32(v.z); d[3] = f2tf32(v.w);
        }
        #pragma unroll
        for (int iw = 0; iw < 4; iw++) {
            int idx = tid + iw * 256;
            int kk = idx >> 5, jq = idx & 31;
            int k = c * 32 + kk;
            const float* wsrc = (jq < 16) ? (Wa + k * 64 + jq * 4)
                                          : (Wb + k * 64 + jq * 4 - 64);
            float4 v = *(const float4*)wsrc;
            unsigned* d = sW + kk * PW + jq * 4;
            d[0] = f2tf32(v.x); d[1] = f2tf32(v.y);
            d[2] = f2tf32(v.z); d[3] = f2tf32(v.w);
        }
        __syncthreads();

        #pragma unroll
        for (int ks = 0; ks < 4; ks++) {
            int k0 = ks * 8;
            unsigned a[2][4];
            #pragma unroll
            for (int mt = 0; mt < 2; mt++) {
                int row = wm * 32 + mt * 16 + gid;
                a[mt][0] = sX[row * PX + k0 + ctid];
                a[mt][1] = sX[(row + 8) * PX + k0 + ctid];
                a[mt][2] = sX[row * PX + k0 + ctid + 4];
                a[mt][3] = sX[(row + 8) * PX + k0 + ctid + 4];
            }
            #pragma unroll
            for (int nt = 0; nt < 8; nt++) {
                int j = wn * 64 + nt * 8 + gid;
                unsigned b0 = sW[(k0 + ctid) * PW + j];
                unsigned b1 = sW[(k0 + ctid + 4) * PW + j];
                MMA_TF32(acc[0][nt], a[0], b0, b1);
                MMA_TF32(acc[1][nt], a[1], b0, b1);
            }
        }
    }

    #pragma unroll
    for (int mt = 0; mt < 2; mt++) {
        int n0 = base + wm * 32 + mt * 16 + gid;
        int n1 = n0 + 8;
        #pragma unroll
        for (int nt = 0; nt < 8; nt++) {
            int j = wn * 64 + nt * 8 + 2 * ctid;
            float* a = acc[mt][nt];
            if (n0 < N_NODES) {
                if (j < 64)
                    *(__half2*)(g_t1h + (size_t)n0 * 64 + j) = __floats2half2_rn(a[0], a[1]);
                else
                    *(float2*)(g_u1 + (size_t)n0 * 64 + (j - 64)) = make_float2(a[0], a[1]);
            }
            if (n1 < N_NODES) {
                if (j < 64)
                    *(__half2*)(g_t1h + (size_t)n1 * 64 + j) = __floats2half2_rn(a[2], a[3]);
                else
                    *(float2*)(g_u1 + (size_t)n1 * 64 + (j - 64)) = make_float2(a[2], a[3]);
            }
        }
    }
}

// ---------------- layer-2 GEMM via tf32 tensor cores ----------------
__global__ __launch_bounds__(256, 2)
void gemmD_kernel(const float* __restrict__ Wa,   // [64, 32] = W2n
                  const float* __restrict__ Wb) { // [64, 32] = W2s
    constexpr int PX = 36;
    constexpr int PW = 72;
    const float* src = g_h;
    __shared__ unsigned sX[128 * PX];
    __shared__ unsigned sW[32 * PW];

    int tid  = threadIdx.x;
    int base = blockIdx.x * 128;
    int w    = tid >> 5;
    int lane = tid & 31;
    int wm   = w & 3;
    int wn   = w >> 2;
    int gid  = lane >> 2;
    int ctid = lane & 3;

    int k4 = tid & 7;
    int r_[4], nc_[4];
    #pragma unroll
    for (int it = 0; it < 4; it++) {
        r_[it] = (tid + it * 256) >> 3;
        int n = base + r_[it];
        nc_[it] = (n < N_NODES) ? n : (N_NODES - 1);
    }

    float acc[2][4][4];
    #pragma unroll
    for (int mt = 0; mt < 2; mt++)
        #pragma unroll
        for (int nt = 0; nt < 4; nt++)
            #pragma unroll
            for (int i = 0; i < 4; i++) acc[mt][nt][i] = 0.0f;

    #pragma unroll 1
    for (int c = 0; c < 2; c++) {
        if (c > 0) __syncthreads();
        #pragma unroll
        for (int it = 0; it < 4; it++) {
            float4 v = *(const float4*)(src + (size_t)nc_[it] * 64 + c * 32 + k4 * 4);
            unsigned* d = sX + r_[it] * PX + k4 * 4;
            d[0] = f2tf32(v.x); d[1] = f2tf32(v.y);
            d[2] = f2tf32(v.z); d[3] = f2tf32(v.w);
        }
        #pragma unroll
        for (int iw = 0; iw < 2; iw++) {
            int idx = tid + iw * 256;
            int kk = idx >> 4, jq = idx & 15;
            int k = c * 32 + kk;
            const float* wsrc = (jq < 8) ? (Wa + k * 32 + jq * 4)
                                         : (Wb + k * 32 + (jq - 8) * 4);
            float4 v = *(const float4*)wsrc;
            unsigned* d = sW + kk * PW + jq * 4;
            d[0] = f2tf32(v.x); d[1] = f2tf32(v.y);
            d[2] = f2tf32(v.z); d[3] = f2tf32(v.w);
        }
        __syncthreads();

        #pragma unroll
        for (int ks = 0; ks < 4; ks++) {
            int k0 = ks * 8;
            unsigned a[2][4];
            #pragma unroll
            for (int mt = 0; mt < 2; mt++) {
                int row = wm * 32 + mt * 16 + gid;
                a[mt][0] = sX[row * PX + k0 + ctid];
                a[mt][1] = sX[(row + 8) * PX + k0 + ctid];
                a[mt][2] = sX[row * PX + k0 + ctid + 4];
                a[mt][3] = sX[(row + 8) * PX + k0 + ctid + 4];
            }
            #pragma unroll
            for (int nt = 0; nt < 4; nt++) {
                int j = wn * 32 + nt * 8 + gid;
                unsigned b0 = sW[(k0 + ctid) * PW + j];
                unsigned b1 = sW[(k0 + ctid + 4) * PW + j];
                MMA_TF32(acc[0][nt], a[0], b0, b1);
                MMA_TF32(acc[1][nt], a[1], b0, b1);
            }
        }
    }

    #pragma unroll
    for (int mt = 0; mt < 2; mt++) {
        int n0 = base + wm * 32 + mt * 16 + gid;
        int n1 = n0 + 8;
        #pragma unroll
        for (int nt = 0; nt < 4; nt++) {
            int j = wn * 32 + nt * 8 + 2 * ctid;
            float* a = acc[mt][nt];
            if (n0 < N_NODES) {
                if (j < 32)
                    *(__half2*)(g_t2h + (size_t)n0 * 32 + j) = __floats2half2_rn(a[0], a[1]);
                else
                    *(float2*)(g_u2 + (size_t)n0 * 32 + (j - 32)) = make_float2(a[0], a[1]);
            }
            if (n1 < N_NODES) {
                if (j < 32)
                    *(__half2*)(g_t2h + (size_t)n1 * 32 + j) = __floats2half2_rn(a[2], a[3]);
                else
                    *(float2*)(g_u2 + (size_t)n1 * 32 + (j - 32)) = make_float2(a[2], a[3]);
            }
        }
    }
}

// ---------------- gather-mean + epilogue kernels (fp16 uint4 gathers) ----------------
// layer 1: 8 lanes/node, 16B loads; h = relu(mean(t1)+u1+b1)
__global__ __launch_bounds__(256)
void aggH_kernel(const float* __restrict__ b1) {
    int tid = threadIdx.x;
    int g = tid >> 3;                    // 32 nodes/block
    int c = tid & 7;                     // 8 halves per lane
    int n = blockIdx.x * 32 + g;
    if (n >= N_NODES) return;
    int start = g_start[n], deg = g_deg[n], end = start + deg;
    float acc[8] = {0.f, 0.f, 0.f, 0.f, 0.f, 0.f, 0.f, 0.f};
    int i = start;
    for (; i + 3 < end; i += 4) {
        int s0 = g_col[i], s1 = g_col[i + 1], s2 = g_col[i + 2], s3 = g_col[i + 3];
        uint4 v0 = *(const uint4*)(g_t1h + (size_t)s0 * 64 + c * 8);
        uint4 v1 = *(const uint4*)(g_t1h + (size_t)s1 * 64 + c * 8);
        uint4 v2 = *(const uint4*)(g_t1h + (size_t)s2 * 64 + c * 8);
        uint4 v3 = *(const uint4*)(g_t1h + (size_t)s3 * 64 + c * 8);
        acc_h8(acc, v0); acc_h8(acc, v1); acc_h8(acc, v2); acc_h8(acc, v3);
    }
    for (; i < end; i++) {
        int s0 = g_col[i];
        uint4 v0 = *(const uint4*)(g_t1h + (size_t)s0 * 64 + c * 8);
        acc_h8(acc, v0);
    }
    float inv = 1.0f / fmaxf((float)deg, 1.0f);
    float4 ua = *(const float4*)(g_u1 + (size_t)n * 64 + c * 8);
    float4 ub = *(const float4*)(g_u1 + (size_t)n * 64 + c * 8 + 4);
    float4 ba = *(const float4*)(b1 + c * 8);
    float4 bbv = *(const float4*)(b1 + c * 8 + 4);
    float4 oa, ob;
    oa.x = fmaxf(fmaf(acc[0], inv, ua.x + ba.x), 0.0f);
    oa.y = fmaxf(fmaf(acc[1], inv, ua.y + ba.y), 0.0f);
    oa.z = fmaxf(fmaf(acc[2], inv, ua.z + ba.z), 0.0f);
    oa.w = fmaxf(fmaf(acc[3], inv, ua.w + ba.w), 0.0f);
    ob.x = fmaxf(fmaf(acc[4], inv, ub.x + bbv.x), 0.0f);
    ob.y = fmaxf(fmaf(acc[5], inv, ub.y + bbv.y), 0.0f);
    ob.z = fmaxf(fmaf(acc[6], inv, ub.z + bbv.z), 0.0f);
    ob.w = fmaxf(fmaf(acc[7], inv, ub.w + bbv.w), 0.0f);
    *(float4*)(g_h + (size_t)n * 64 + c * 8)     = oa;
    *(float4*)(g_h + (size_t)n * 64 + c * 8 + 4) = ob;
}

// layer 2: 4 lanes/node, 16B loads; out = mean(t2)+u2+b2
__global__ __launch_bounds__(256)
void agg_final_kernel(const float* __restrict__ b2, float* __restrict__ out) {
    int tid = threadIdx.x;
    int g = tid >> 2;                    // 64 nodes/block
    int c = tid & 3;                     // 8 halves per lane
    int n = blockIdx.x * 64 + g;
    if (n >= N_NODES) return;
    int start = g_start[n], deg = g_deg[n], end = start + deg;
    float acc[8] = {0.f, 0.f, 0.f, 0.f, 0.f, 0.f, 0.f, 0.f};
    int i = start;
    for (; i + 3 < end; i += 4) {
        int s0 = g_col[i], s1 = g_col[i + 1], s2 = g_col[i + 2], s3 = g_col[i + 3];
        uint4 v0 = *(const uint4*)(g_t2h + (size_t)s0 * 32 + c * 8);
        uint4 v1 = *(const uint4*)(g_t2h + (size_t)s1 * 32 + c * 8);
        uint4 v2 = *(const uint4*)(g_t2h + (size_t)s2 * 32 + c * 8);
        uint4 v3 = *(const uint4*)(g_t2h + (size_t)s3 * 32 + c * 8);
        acc_h8(acc, v0); acc_h8(acc, v1); acc_h8(acc, v2); acc_h8(acc, v3);
    }
    for (; i < end; i++) {
        int s0 = g_col[i];
        uint4 v0 = *(const uint4*)(g_t2h + (size_t)s0 * 32 + c * 8);
        acc_h8(acc, v0);
    }
    float inv = 1.0f / fmaxf((float)deg, 1.0f);
    float4 ua = *(const float4*)(g_u2 + (size_t)n * 32 + c * 8);
    float4 ub = *(const float4*)(g_u2 + (size_t)n * 32 + c * 8 + 4);
    float4 ba = *(const float4*)(b2 + c * 8);
    float4 bbv = *(const float4*)(b2 + c * 8 + 4);
    float4 oa, ob;
    oa.x = fmaf(acc[0], inv, ua.x + ba.x);
    oa.y = fmaf(acc[1], inv, ua.y + ba.y);
    oa.z = fmaf(acc[2], inv, ua.z + ba.z);
    oa.w = fmaf(acc[3], inv, ua.w + ba.w);
    ob.x = fmaf(acc[4], inv, ub.x + bbv.x);
    ob.y = fmaf(acc[5], inv, ub.y + bbv.y);
    ob.z = fmaf(acc[6], inv, ub.z + bbv.z);
    ob.w = fmaf(acc[7], inv, ub.w + bbv.w);
    *(float4*)(out + (size_t)n * 32 + c * 8)     = oa;
    *(float4*)(out + (size_t)n * 32 + c * 8 + 4) = ob;
}

// ---------------- launch ----------------
extern "C" void kernel_launch(void* const* d_in, const int* in_sizes, int n_in,
                              void* d_out, int out_size) {
    const float* x   = (const float*)d_in[0];
    const void*  ei  = d_in[1];
    const float* W1n = (const float*)d_in[2];
    const float* W1s = (const float*)d_in[3];
    const float* b1  = (const float*)d_in[4];
    const float* W2n = (const float*)d_in[5];
    const float* W2s = (const float*)d_in[6];
    const float* b2  = (const float*)d_in[7];
    float* out = (float*)d_out;
    int E = in_sizes[1] / 2;

    cudaStream_t s2;
    cudaStreamCreate(&s2);
    cudaEvent_t evFork, evJoin;
    cudaEventCreateWithFlags(&evFork, cudaEventDisableTiming);
    cudaEventCreateWithFlags(&evJoin, cudaEventDisableTiming);

    cudaEventRecord(evFork, 0);
    cudaStreamWaitEvent(s2, evFork, 0);

    // CSR build on side stream (4 edges/thread)
    count_kernel<<<(E / 4 + 256) / 256, 256, 0, s2>>>(ei, E);
    offs_kernel<<<(N_NODES + 255) / 256, 256, 0, s2>>>();
    fill_kernel<<<(E / 4 + 256) / 256, 256, 0, s2>>>(ei, E);
    cudaEventRecord(evJoin, s2);

    // layer-1 GEMM (tensor cores) on main stream, concurrent with CSR build
    gemmA_kernel<<<(N_NODES + 127) / 128, 256>>>(x, W1n, W1s);

    cudaStreamWaitEvent(0, evJoin, 0);

    aggH_kernel<<<(N_NODES + 31) / 32, 256>>>(b1);
    gemmD_kernel<<<(N_NODES + 127) / 128, 256>>>(W2n, W2s);
    agg_final_kernel<<<(N_NODES + 63) / 64, 256>>>(b2, out);

    cudaEventDestroy(evFork);
    cudaEventDestroy(evJoin);
    cudaStreamDestroy(s2);
}